// round 7
// baseline (speedup 1.0000x reference)
#include <cuda_runtime.h>

typedef unsigned long long u64;

#define NRAYS 4096
#define SMAIN 64
#define NG    4
#define DHID  128
#define IMGH  900
#define IMGW  1600
constexpr int PP = 32;   // points per decode block
constexpr int PH = 16;   // f32x2 pairs

// ---- device scratch (no cudaMalloc allowed) ----
__device__ __align__(16) float g_vox[8 * 200 * 200 * 128];
__device__ float g_dirs[NRAYS * 3], g_view[NRAYS * 3], g_cam[NRAYS * 3];
__device__ float g_outg[NRAYS * NG * 2];
__device__ float g_means[NRAYS * NG], g_stds[NRAYS * NG];
__device__ float g_dall[NRAYS * SMAIN];
__device__ __align__(16) float g_outm[NRAYS * SMAIN * 4];
__device__ float g_kl[NRAYS], g_d2c[NRAYS], g_colL[NRAYS], g_rn[NRAYS], g_rd[NRAYS];

// ---- f32x2 helpers ----
__device__ __forceinline__ u64 pk2(float v) {
    u64 r; asm("mov.b64 %0, {%1, %1};" : "=l"(r) : "f"(v)); return r;
}
__device__ __forceinline__ void fma2(u64 &d, u64 a, u64 b) {
    asm("fma.rn.f32x2 %0, %1, %2, %0;" : "+l"(d) : "l"(a), "l"(b));
}
__device__ __forceinline__ void upk2(u64 v, float &lo, float &hi) {
    asm("mov.b64 {%0, %1}, %2;" : "=f"(lo), "=f"(hi) : "l"(v));
}
__device__ __forceinline__ void mmloop(u64 *acc, const u64 *__restrict__ src,
                                       const float *__restrict__ W, int j, int K) {
#pragma unroll 4
    for (int k = 0; k < K; k++) {
        u64 w = pk2(W[k * DHID + j]);
        const u64 *s = src + k * PH;
#pragma unroll
        for (int i = 0; i < PH; i++) fma2(acc[i], s[i], w);
    }
}

// ---- 1) bev (1,1024,200,200) -> vox (8,200,200,128) ----
__global__ void transpose_kernel(const float *__restrict__ bev) {
    __shared__ float tile[32][33];
    int dh = blockIdx.z, d = dh / 200, h = dh - d * 200;
    int w0 = blockIdx.x * 32, c0 = blockIdx.y * 32;
    int tx = threadIdx.x, ty = threadIdx.y;
#pragma unroll
    for (int i = 0; i < 32; i += 8) {
        int c = c0 + ty + i, w = w0 + tx;
        if (w < 200) tile[ty + i][tx] = bev[(c * 8 + d) * 40000 + h * 200 + w];
    }
    __syncthreads();
#pragma unroll
    for (int i = 0; i < 32; i += 8) {
        int w = w0 + ty + i, c = c0 + tx;
        if (w < 200) g_vox[((d * 200 + h) * 200 + w) * 128 + c] = tile[tx][ty + i];
    }
}

// ---- 2) per-ray setup ----
__global__ void setup_kernel(const float *__restrict__ K4,
                             const float *__restrict__ s2i,
                             const float *__restrict__ pix) {
    int r = blockIdx.x * blockDim.x + threadIdx.x;
    if (r >= NRAYS) return;
    float a = K4[0], b = K4[1], c = K4[2], d = K4[3], e = K4[4], f = K4[5];
    float g = K4[6], h = K4[7], i9 = K4[8];
    float A = e * i9 - f * h, B = c * h - b * i9, C = b * f - c * e;
    float D = f * g - d * i9, E = a * i9 - c * g, F = c * d - a * f;
    float G = d * h - e * g, H = b * g - a * h, I = a * e - b * d;
    float idet = 1.f / (a * A + b * D + c * G);
    float u = pix[2 * r], v = pix[2 * r + 1];
    float cx = (A * u + B * v + C) * idet;
    float cy = (D * u + E * v + F) * idet;
    float cz = (G * u + H * v + I) * idet;
    g_cam[3 * r] = cx; g_cam[3 * r + 1] = cy; g_cam[3 * r + 2] = cz;
    float dx = s2i[0] * cx + s2i[1] * cy + s2i[2]  * cz;
    float dy = s2i[4] * cx + s2i[5] * cy + s2i[6]  * cz;
    float dz = s2i[8] * cx + s2i[9] * cy + s2i[10] * cz;
    g_dirs[3 * r] = dx; g_dirs[3 * r + 1] = dy; g_dirs[3 * r + 2] = dz;
    float inv = rsqrtf(dx * dx + dy * dy + dz * dz);
    g_view[3 * r] = dx * inv; g_view[3 * r + 1] = dy * inv; g_view[3 * r + 2] = dz * inv;
}

// ---- 3) ResNet-MLP decode; region A (s_r) overlays s_x ----
template <bool GAUSS>
__global__ void __launch_bounds__(128) decode_kernel(
    const float *__restrict__ s2i,
    const float *__restrict__ Win, const float *__restrict__ bin,
    const float *__restrict__ Wz,  const float *__restrict__ bz,
    const float *__restrict__ W0,  const float *__restrict__ b0,
    const float *__restrict__ W1,  const float *__restrict__ b1,
    const float *__restrict__ Wout,const float *__restrict__ bout)
{
    constexpr int S = GAUSS ? NG : SMAIN;
    constexpr int DOUT = GAUSS ? 2 : 4;
    extern __shared__ float sm[];
    float *s_r = sm;                 // 128*PP, overlays s_x
    float *s_x = sm;                 // 42*PP (dead after first matmul)
    float *s_z = sm + DHID * PP;
    float *s_h = s_z + DHID * PP;
    __shared__ float s_pt[PP][3], s_vd[PP][3], s_f[PP][3];
    __shared__ int   s_base[PP], s_val[PP];

    const int j = threadIdx.x;
    const int n0 = blockIdx.x * PP;

    if (j < PP) {
        int n = n0 + j, r = n / S, s = n - r * S;
        float dpt = GAUSS ? ((float)s + 0.5f) * 25.0f : g_dall[n];
        float px = s2i[3]  + g_dirs[3 * r]     * dpt;
        float py = s2i[7]  + g_dirs[3 * r + 1] * dpt;
        float pz = s2i[11] + g_dirs[3 * r + 2] * dpt;
        s_pt[j][0] = px; s_pt[j][1] = py; s_pt[j][2] = pz;
        s_vd[j][0] = g_view[3 * r]; s_vd[j][1] = g_view[3 * r + 1]; s_vd[j][2] = g_view[3 * r + 2];
        float gx = (px + 51.2f) * (199.0f / 102.4f);
        float gy = (py + 51.2f) * (199.0f / 102.4f);
        float gz = (pz + 5.0f) * (7.0f / 8.0f);
        s_val[j] = (gx >= 0.f) & (gx <= 199.f) & (gy >= 0.f) & (gy <= 199.f) &
                   (gz >= 0.f) & (gz <= 7.f);
        int x0 = min(max((int)floorf(gx), 0), 198);
        int y0 = min(max((int)floorf(gy), 0), 198);
        int z0 = min(max((int)floorf(gz), 0), 6);
        s_f[j][0] = fminf(fmaxf(gx - (float)x0, 0.f), 1.f);
        s_f[j][1] = fminf(fmaxf(gy - (float)y0, 0.f), 1.f);
        s_f[j][2] = fminf(fmaxf(gz - (float)z0, 0.f), 1.f);
        s_base[j] = ((z0 * 200 + x0) * 200 + y0) * 128;
    }
    __syncthreads();

    if (j < 42) {   // pos-enc features, layout [k][P]
#pragma unroll 4
        for (int p = 0; p < PP; p++) {
            float v;
            if (j < 3) v = s_pt[p][j];
            else if (j < 39) {
                int q = j - 3, f = q / 6, t = q - f * 6;
                float fr = 3.14159265358979323846f * (float)(1 << f);
                float xx = ((t < 3) ? s_pt[p][t] : s_pt[p][t - 3]) * fr;
                v = (t < 3) ? sinf(xx) : cosf(xx);
            } else v = s_vd[p][j - 39];
            s_x[j * PP + p] = v;
        }
    }
    {   // trilinear gather, channel = j
#pragma unroll 2
        for (int p = 0; p < PP; p++) {
            float zv = 0.f;
            if (s_val[p]) {
                const float *vp = g_vox + s_base[p] + j;
                float fx = s_f[p][0], fy = s_f[p][1], fz = s_f[p][2];
                float ox = 1.f - fx, oy = 1.f - fy, oz = 1.f - fz;
                float c00 = vp[0]       * ox + vp[25600]   * fx;
                float c01 = vp[128]     * ox + vp[25728]   * fx;
                float c10 = vp[5120000] * ox + vp[5145600] * fx;
                float c11 = vp[5120128] * ox + vp[5145728] * fx;
                zv = (c00 * oy + c01 * fy) * oz + (c10 * oy + c11 * fy) * fz;
            }
            s_z[j * PP + p] = zv;
        }
    }
    __syncthreads();

    const u64 *x2 = (const u64 *)s_x;
    const u64 *z2 = (const u64 *)s_z;
    const u64 *r2 = (const u64 *)s_r;
    u64 *h2 = (u64 *)s_h;
    u64 acc[PH];

    {   // h = x @ Win + bin
        u64 bb = pk2(bin[j]);
#pragma unroll
        for (int i = 0; i < PH; i++) acc[i] = bb;
        mmloop(acc, x2, Win, j, 42);
#pragma unroll
        for (int i = 0; i < PH; i++) h2[j * PH + i] = acc[i];
    }
    __syncthreads();

    for (int blk = 0; blk < 3; blk++) {
        const float *Wzi = Wz + blk * 16384, *bzi = bz + blk * 128;
        const float *W0i = W0 + blk * 16384, *b0i = b0 + blk * 128;
        const float *W1i = W1 + blk * 16384, *b1i = b1 + blk * 128;

        u64 bb = pk2(bzi[j]);                 // h += z@Wz+bz ; r = relu(h)
#pragma unroll
        for (int i = 0; i < PH; i++) acc[i] = bb;
        mmloop(acc, z2, Wzi, j, DHID);
        __syncthreads();                       // s_r overlays s_x; also guard h read
#pragma unroll
        for (int i = 0; i < PH; i++) {
            float lo, hi; upk2(acc[i], lo, hi);
            float h0 = s_h[j * PP + 2 * i] + lo, h1 = s_h[j * PP + 2 * i + 1] + hi;
            s_h[j * PP + 2 * i] = h0; s_h[j * PP + 2 * i + 1] = h1;
            s_r[j * PP + 2 * i] = fmaxf(h0, 0.f); s_r[j * PP + 2 * i + 1] = fmaxf(h1, 0.f);
        }
        __syncthreads();

        bb = pk2(b0i[j]);                      // net = relu(h)@W0+b0 ; r = relu(net)
#pragma unroll
        for (int i = 0; i < PH; i++) acc[i] = bb;
        mmloop(acc, r2, W0i, j, DHID);
        __syncthreads();
#pragma unroll
        for (int i = 0; i < PH; i++) {
            float lo, hi; upk2(acc[i], lo, hi);
            s_r[j * PP + 2 * i] = fmaxf(lo, 0.f); s_r[j * PP + 2 * i + 1] = fmaxf(hi, 0.f);
        }
        __syncthreads();

        bb = pk2(b1i[j]);                      // h += relu(net)@W1+b1
#pragma unroll
        for (int i = 0; i < PH; i++) acc[i] = bb;
        mmloop(acc, r2, W1i, j, DHID);
        __syncthreads();
#pragma unroll
        for (int i = 0; i < PH; i++) {
            float lo, hi; upk2(acc[i], lo, hi);
            float h0 = s_h[j * PP + 2 * i] + lo, h1 = s_h[j * PP + 2 * i + 1] + hi;
            s_h[j * PP + 2 * i] = h0; s_h[j * PP + 2 * i + 1] = h1;
            if (blk == 2) {
                s_r[j * PP + 2 * i] = fmaxf(h0, 0.f);
                s_r[j * PP + 2 * i + 1] = fmaxf(h1, 0.f);
            }
        }
        __syncthreads();
    }

    if (j < PP * DOUT) {   // out = relu(h)@Wout+bout
        int p = j / DOUT, o = j - p * DOUT;
        float a = bout[o];
#pragma unroll 8
        for (int k = 0; k < DHID; k++) a += s_r[k * PP + p] * Wout[k * DOUT + o];
        (GAUSS ? g_outg : g_outm)[(n0 + p) * DOUT + o] = a;
    }
}

// ---- 4) gaussian params + depth samples + per-ray sort ----
__global__ void gprep_kernel() {
    int r = blockIdx.x * blockDim.x + threadIdx.x;
    if (r >= NRAYS) return;
    float m[NG], sd[NG], d[SMAIN];
#pragma unroll
    for (int g = 0; g < NG; g++) {
        float o0 = g_outg[(r * NG + g) * 2], o1 = g_outg[(r * NG + g) * 2 + 1];
        m[g] = ((float)g + 0.5f) * 25.f + tanhf(o0) * 12.5f;
        sd[g] = 1.f / (1.f + expf(-o1)) * 5.f + 0.001f;
        g_means[r * NG + g] = m[g]; g_stds[r * NG + g] = sd[g];
    }
    for (int i = 0; i < 32; i++) d[i] = 0.5f + (float)i * (99.5f / 31.f);
    int idx = 32;
    for (int g = 0; g < NG; g++)
        for (int jj = 0; jj < 8; jj++)
            d[idx++] = m[g] + (-1.f + (float)jj * (2.f / 7.f)) * 2.f * sd[g];
    for (int i = 0; i < SMAIN; i++) d[i] = fminf(fmaxf(d[i], 0.01f), 100.f);
    for (int i = 1; i < SMAIN; i++) {
        float v = d[i]; int k = i - 1;
        while (k >= 0 && d[k] > v) { d[k + 1] = d[k]; k--; }
        d[k + 1] = v;
    }
    for (int i = 0; i < SMAIN; i++) g_dall[r * SMAIN + i] = d[i];
}

// ---- 5) rendering + losses ----
__device__ __forceinline__ void samp_img(const float *__restrict__ img,
                                         float u, float v, float *o3) {
    float x0f = fminf(fmaxf(floorf(u), 0.f), (float)(IMGW - 2));
    float y0f = fminf(fmaxf(floorf(v), 0.f), (float)(IMGH - 2));
    int x0 = (int)x0f, y0 = (int)y0f;
    float fx = fminf(fmaxf(u - x0f, 0.f), 1.f), fy = fminf(fmaxf(v - y0f, 0.f), 1.f);
    float w00 = (1.f - fx) * (1.f - fy), w10 = fx * (1.f - fy);
    float w01 = (1.f - fx) * fy, w11 = fx * fy;
#pragma unroll
    for (int c = 0; c < 3; c++) {
        int b = c * IMGH * IMGW + y0 * IMGW + x0;
        o3[c] = img[b] * w00 + img[b + 1] * w10 + img[b + IMGW] * w01 + img[b + IMGW + 1] * w11;
    }
}

__global__ void render_kernel(const float *__restrict__ src, const float *__restrict__ tgt,
                              const float *__restrict__ K4, const float *__restrict__ s2t,
                              const float *__restrict__ pix, float *__restrict__ dout) {
    int r = blockIdx.x * blockDim.x + threadIdx.x;
    if (r >= NRAYS) return;
    const float EPSf = 1e-6f;
    float d[SMAIN], w[SMAIN], q[SMAIN];
    for (int s = 0; s < SMAIN; s++) d[s] = g_dall[r * SMAIN + s];
    float T = 1.f, depth = 0.f, c0 = 0.f, c1 = 0.f, c2 = 0.f, wsum = 0.f;
    for (int s = 0; s < SMAIN; s++) {
        float4 o = reinterpret_cast<const float4 *>(g_outm)[r * SMAIN + s];
        float delta = (s < SMAIN - 1) ? (d[s + 1] - d[s]) : 1e10f;
        float alpha = 1.f - expf(-fmaxf(o.x, 0.f) * delta);
        float ww = alpha * T;
        T *= (1.f - alpha + 1e-10f);
        w[s] = ww; wsum += ww; depth += ww * d[s];
        c0 += ww / (1.f + expf(-o.y));
        c1 += ww / (1.f + expf(-o.z));
        c2 += ww / (1.f + expf(-o.w));
    }
    float m[NG], sd[NG], ls[NG];
#pragma unroll
    for (int g = 0; g < NG; g++) {
        m[g] = g_means[r * NG + g]; sd[g] = g_stds[r * NG + g]; ls[g] = logf(sd[g]);
    }
    float qsum = 0.f;
    for (int s = 0; s < SMAIN; s++) {
        float qq = 0.f;
#pragma unroll
        for (int g = 0; g < NG; g++) {
            float t = (d[s] - m[g]) / sd[g];
            qq += expf(-0.5f * t * t - ls[g]);
        }
        q[s] = qq * 0.25f; qsum += q[s];
    }
    float kl = 0.f;
    for (int s = 0; s < SMAIN; s++) {
        float pw = w[s] / (wsum + EPSf), qn = q[s] / (qsum + EPSf);
        kl += pw * (logf(pw + EPSf) - logf(qn + EPSf));
    }
    float d2c = 1e30f;
#pragma unroll
    for (int g = 0; g < NG; g++) d2c = fminf(d2c, fabsf(m[g] - depth));

    float sc[3]; samp_img(src, pix[2 * r], pix[2 * r + 1], sc);
    float closs = fabsf(sc[0] - c0) + fabsf(sc[1] - c1) + fabsf(sc[2] - c2);

    float cx = g_cam[3 * r] * depth, cy = g_cam[3 * r + 1] * depth, cz = g_cam[3 * r + 2] * depth;
    float tx = s2t[0] * cx + s2t[1] * cy + s2t[2]  * cz + s2t[3];
    float ty = s2t[4] * cx + s2t[5] * cy + s2t[6]  * cz + s2t[7];
    float tz = s2t[8] * cx + s2t[9] * cy + s2t[10] * cz + s2t[11];
    float pxp = K4[0] * tx + K4[1] * ty + K4[2] * tz;
    float pyp = K4[3] * tx + K4[4] * ty + K4[5] * tz;
    float pzp = K4[6] * tx + K4[7] * ty + K4[8] * tz;
    float tc[3]; samp_img(tgt, pxp / (pzp + EPSf), pyp / (pzp + EPSf), tc);
    float mask = (depth < 30.f) ? 1.f : 0.f;
    g_kl[r] = kl; g_d2c[r] = d2c; g_colL[r] = closs;
    g_rn[r] = mask * (fabsf(tc[0] - sc[0]) + fabsf(tc[1] - sc[1]) + fabsf(tc[2] - sc[2])) * (1.f / 3.f);
    g_rd[r] = mask;
    dout[1 + r] = depth;
    dout[1 + NRAYS + 3 * r + 0] = c0;
    dout[1 + NRAYS + 3 * r + 1] = c1;
    dout[1 + NRAYS + 3 * r + 2] = c2;
}

// ---- 6) deterministic scalar reduction ----
__global__ void reduce_kernel(float *__restrict__ dout) {
    __shared__ float sm[5][256];
    int t = threadIdx.x;
    float a[5] = {0, 0, 0, 0, 0};
    for (int r = t; r < NRAYS; r += 256) {
        a[0] += g_kl[r]; a[1] += g_d2c[r]; a[2] += g_colL[r]; a[3] += g_rn[r]; a[4] += g_rd[r];
    }
    for (int c = 0; c < 5; c++) sm[c][t] = a[c];
    __syncthreads();
    for (int s = 128; s > 0; s >>= 1) {
        if (t < s) for (int c = 0; c < 5; c++) sm[c][t] += sm[c][t + s];
        __syncthreads();
    }
    if (t == 0)
        dout[0] = sm[0][0] * (1.f / NRAYS) + 0.01f * sm[1][0] * (1.f / NRAYS) +
                  sm[2][0] * (1.f / (3.f * NRAYS)) + sm[3][0] / (sm[4][0] + 1e-6f);
}

extern "C" void kernel_launch(void* const* d_in, const int* in_sizes, int n_in,
                              void* d_out, int out_size) {
    const float *bev = (const float *)d_in[0];
    const float *src = (const float *)d_in[1];
    const float *tgt = (const float *)d_in[2];
    const float *K4  = (const float *)d_in[3];
    const float *s2i = (const float *)d_in[4];
    const float *s2t = (const float *)d_in[5];
    const float *pix = (const float *)d_in[6];
    const float *const *m1 = (const float *const *)&d_in[7];   // main MLP (4 out)
    const float *const *m2 = (const float *const *)&d_in[17];  // gauss MLP (2 out)
    float *dout = (float *)d_out;

    int smem = 3 * DHID * PP * 4;   // 49152
    cudaFuncSetAttribute(decode_kernel<true>,  cudaFuncAttributeMaxDynamicSharedMemorySize, smem);
    cudaFuncSetAttribute(decode_kernel<false>, cudaFuncAttributeMaxDynamicSharedMemorySize, smem);

    transpose_kernel<<<dim3(7, 4, 1600), dim3(32, 8)>>>(bev);
    setup_kernel<<<16, 256>>>(K4, s2i, pix);
    decode_kernel<true><<<NRAYS * NG / PP, 128, smem>>>(
        s2i, m2[0], m2[1], m2[2], m2[3], m2[4], m2[5], m2[6], m2[7], m2[8], m2[9]);
    gprep_kernel<<<16, 256>>>();
    decode_kernel<false><<<NRAYS * SMAIN / PP, 128, smem>>>(
        s2i, m1[0], m1[1], m1[2], m1[3], m1[4], m1[5], m1[6], m1[7], m1[8], m1[9]);
    render_kernel<<<16, 256>>>(src, tgt, K4, s2t, pix, dout);
    reduce_kernel<<<1, 256>>>(dout);
}

// round 9
// speedup vs baseline: 1.0312x; 1.0312x over previous
#include <cuda_runtime.h>

typedef unsigned long long u64;

#define NRAYS 4096
#define SMAIN 64
#define NG    4
#define DHID  128
#define IMGH  900
#define IMGW  1600

// ---- device scratch (no cudaMalloc allowed) ----
__device__ __align__(16) float g_vox[8 * 200 * 200 * 128];
__device__ float g_dirs[NRAYS * 3], g_view[NRAYS * 3], g_cam[NRAYS * 3];
__device__ float g_outg[NRAYS * NG * 2];
__device__ float g_means[NRAYS * NG], g_stds[NRAYS * NG];
__device__ float g_dall[NRAYS * SMAIN];
__device__ __align__(16) float g_outm[NRAYS * SMAIN * 4];
__device__ float g_kl[NRAYS], g_d2c[NRAYS], g_colL[NRAYS], g_rn[NRAYS], g_rd[NRAYS];

// ---- f32x2 helpers ----
__device__ __forceinline__ u64 pk2(float v) {
    u64 r; asm("mov.b64 %0, {%1, %1};" : "=l"(r) : "f"(v)); return r;
}
__device__ __forceinline__ void fma2(u64 &d, u64 a, u64 b) {
    asm("fma.rn.f32x2 %0, %1, %2, %0;" : "+l"(d) : "l"(a), "l"(b));
}
__device__ __forceinline__ void upk2(u64 v, float &lo, float &hi) {
    asm("mov.b64 {%0, %1}, %2;" : "=f"(lo), "=f"(hi) : "l"(v));
}

constexpr int PP  = 64;   // points per decode block
constexpr int RSU = 34;   // activation row stride (u64)  -> 16B aligned, depad banks
constexpr int RSF = 68;   // activation row stride (floats)

// Register-blocked matmul: thread owns cols (jj, jj+64) x 16 point-pairs.
// Activations in smem laid out [k][point], row stride RSU u64.
__device__ __forceinline__ void mm2(u64 acc[2][16], const u64 *__restrict__ src,
                                    const float *__restrict__ W,
                                    int jj, int half, int K) {
#pragma unroll 2
    for (int k = 0; k < K; k++) {
        u64 w0 = pk2(W[k * DHID + jj]);
        u64 w1 = pk2(W[k * DHID + jj + 64]);
        const ulonglong2 *s = (const ulonglong2 *)(src + k * RSU + half * 16);
#pragma unroll
        for (int i = 0; i < 8; i++) {
            ulonglong2 v = s[i];
            fma2(acc[0][2 * i],     v.x, w0);
            fma2(acc[0][2 * i + 1], v.y, w0);
            fma2(acc[1][2 * i],     v.x, w1);
            fma2(acc[1][2 * i + 1], v.y, w1);
        }
    }
}

// ---- 1) bev (1,1024,200,200) -> vox (8,200,200,128) ----
__global__ void transpose_kernel(const float *__restrict__ bev) {
    __shared__ float tile[32][33];
    int dh = blockIdx.z, d = dh / 200, h = dh - d * 200;
    int w0 = blockIdx.x * 32, c0 = blockIdx.y * 32;
    int tx = threadIdx.x, ty = threadIdx.y;
#pragma unroll
    for (int i = 0; i < 32; i += 8) {
        int c = c0 + ty + i, w = w0 + tx;
        if (w < 200) tile[ty + i][tx] = bev[(c * 8 + d) * 40000 + h * 200 + w];
    }
    __syncthreads();
#pragma unroll
    for (int i = 0; i < 32; i += 8) {
        int w = w0 + ty + i, c = c0 + tx;
        if (w < 200) g_vox[((d * 200 + h) * 200 + w) * 128 + c] = tile[tx][ty + i];
    }
}

// ---- 2) per-ray setup ----
__global__ void setup_kernel(const float *__restrict__ K4,
                             const float *__restrict__ s2i,
                             const float *__restrict__ pix) {
    int r = blockIdx.x * blockDim.x + threadIdx.x;
    if (r >= NRAYS) return;
    float a = K4[0], b = K4[1], c = K4[2], d = K4[3], e = K4[4], f = K4[5];
    float g = K4[6], h = K4[7], i9 = K4[8];
    float A = e * i9 - f * h, B = c * h - b * i9, C = b * f - c * e;
    float D = f * g - d * i9, E = a * i9 - c * g, F = c * d - a * f;
    float G = d * h - e * g, H = b * g - a * h, I = a * e - b * d;
    float idet = 1.f / (a * A + b * D + c * G);
    float u = pix[2 * r], v = pix[2 * r + 1];
    float cx = (A * u + B * v + C) * idet;
    float cy = (D * u + E * v + F) * idet;
    float cz = (G * u + H * v + I) * idet;
    g_cam[3 * r] = cx; g_cam[3 * r + 1] = cy; g_cam[3 * r + 2] = cz;
    float dx = s2i[0] * cx + s2i[1] * cy + s2i[2]  * cz;
    float dy = s2i[4] * cx + s2i[5] * cy + s2i[6]  * cz;
    float dz = s2i[8] * cx + s2i[9] * cy + s2i[10] * cz;
    g_dirs[3 * r] = dx; g_dirs[3 * r + 1] = dy; g_dirs[3 * r + 2] = dz;
    float inv = rsqrtf(dx * dx + dy * dy + dz * dz);
    g_view[3 * r] = dx * inv; g_view[3 * r + 1] = dy * inv; g_view[3 * r + 2] = dz * inv;
}

// ---- 3) ResNet-MLP decode (register-blocked f32x2) ----
template <bool GAUSS>
__global__ void __launch_bounds__(128) decode_kernel(
    const float *__restrict__ s2i,
    const float *__restrict__ Win, const float *__restrict__ bin,
    const float *__restrict__ Wz,  const float *__restrict__ bz,
    const float *__restrict__ W0,  const float *__restrict__ b0,
    const float *__restrict__ W1,  const float *__restrict__ b1,
    const float *__restrict__ Wout,const float *__restrict__ bout)
{
    constexpr int S = GAUSS ? NG : SMAIN;
    constexpr int DOUT = GAUSS ? 2 : 4;
    extern __shared__ float sm[];
    float *s_r = sm;                    // 128*RSF floats, overlays s_x
    float *s_x = sm;                    // rows 0..41 used
    float *s_z = sm + 128 * RSF;
    float *s_h = s_z + 128 * RSF;
    __shared__ float s_pt[PP][3], s_vd[PP][3], s_f[PP][3];
    __shared__ int   s_base[PP], s_val[PP];

    const int j = threadIdx.x;
    const int jj = j & 63, half = j >> 6;
    const int n0 = blockIdx.x * PP;

    if (j < PP) {
        int n = n0 + j, r = n / S, s = n - r * S;
        float dpt = GAUSS ? ((float)s + 0.5f) * 25.0f : g_dall[n];
        float px = s2i[3]  + g_dirs[3 * r]     * dpt;
        float py = s2i[7]  + g_dirs[3 * r + 1] * dpt;
        float pz = s2i[11] + g_dirs[3 * r + 2] * dpt;
        s_pt[j][0] = px; s_pt[j][1] = py; s_pt[j][2] = pz;
        s_vd[j][0] = g_view[3 * r]; s_vd[j][1] = g_view[3 * r + 1]; s_vd[j][2] = g_view[3 * r + 2];
        float gx = (px + 51.2f) * (199.0f / 102.4f);
        float gy = (py + 51.2f) * (199.0f / 102.4f);
        float gz = (pz + 5.0f) * (7.0f / 8.0f);
        s_val[j] = (gx >= 0.f) & (gx <= 199.f) & (gy >= 0.f) & (gy <= 199.f) &
                   (gz >= 0.f) & (gz <= 7.f);
        int x0 = min(max((int)floorf(gx), 0), 198);
        int y0 = min(max((int)floorf(gy), 0), 198);
        int z0 = min(max((int)floorf(gz), 0), 6);
        s_f[j][0] = fminf(fmaxf(gx - (float)x0, 0.f), 1.f);
        s_f[j][1] = fminf(fmaxf(gy - (float)y0, 0.f), 1.f);
        s_f[j][2] = fminf(fmaxf(gz - (float)z0, 0.f), 1.f);
        s_base[j] = ((z0 * 200 + x0) * 200 + y0) * 128;
    }
    __syncthreads();

    if (j < 42) {   // pos-enc features, layout [feature][point]
#pragma unroll 4
        for (int p = 0; p < PP; p++) {
            float v;
            if (j < 3) v = s_pt[p][j];
            else if (j < 39) {
                int q = j - 3, f = q / 6, t = q - f * 6;
                float fr = 3.14159265358979323846f * (float)(1 << f);
                float xx = ((t < 3) ? s_pt[p][t] : s_pt[p][t - 3]) * fr;
                v = (t < 3) ? sinf(xx) : cosf(xx);
            } else v = s_vd[p][j - 39];
            s_x[j * RSF + p] = v;
        }
    }
    {   // trilinear gather, channel = j
#pragma unroll 2
        for (int p = 0; p < PP; p++) {
            float zv = 0.f;
            if (s_val[p]) {
                const float *vp = g_vox + s_base[p] + j;
                float fx = s_f[p][0], fy = s_f[p][1], fz = s_f[p][2];
                float ox = 1.f - fx, oy = 1.f - fy, oz = 1.f - fz;
                float c00 = vp[0]       * ox + vp[25600]   * fx;
                float c01 = vp[128]     * ox + vp[25728]   * fx;
                float c10 = vp[5120000] * ox + vp[5145600] * fx;
                float c11 = vp[5120128] * ox + vp[5145728] * fx;
                zv = (c00 * oy + c01 * fy) * oz + (c10 * oy + c11 * fy) * fz;
            }
            s_z[j * RSF + p] = zv;
        }
    }
    __syncthreads();

    const u64 *x2 = (const u64 *)s_x;
    const u64 *z2 = (const u64 *)s_z;
    const u64 *r2 = (const u64 *)s_r;
    u64    *h2u = (u64 *)s_h;
    float2 *h2f = (float2 *)s_h;
    float2 *r2f = (float2 *)s_r;
    const int i0 = jj * RSU + half * 16;          // this thread's col-0 slot base
    const int i1 = (jj + 64) * RSU + half * 16;   // col-1 slot base
    u64 acc[2][16];

    {   // h = x @ Win + bin
        u64 bb0 = pk2(bin[jj]), bb1 = pk2(bin[jj + 64]);
#pragma unroll
        for (int i = 0; i < 16; i++) { acc[0][i] = bb0; acc[1][i] = bb1; }
        mm2(acc, x2, Win, jj, half, 42);
#pragma unroll
        for (int i = 0; i < 16; i++) { h2u[i0 + i] = acc[0][i]; h2u[i1 + i] = acc[1][i]; }
    }
    __syncthreads();

    for (int blk = 0; blk < 3; blk++) {
        const float *Wzi = Wz + blk * 16384, *bzi = bz + blk * 128;
        const float *W0i = W0 + blk * 16384, *b0i = b0 + blk * 128;
        const float *W1i = W1 + blk * 16384, *b1i = b1 + blk * 128;

        // h += z @ Wz + bz ; r = relu(h)
        u64 bb0 = pk2(bzi[jj]), bb1 = pk2(bzi[jj + 64]);
#pragma unroll
        for (int i = 0; i < 16; i++) { acc[0][i] = bb0; acc[1][i] = bb1; }
        mm2(acc, z2, Wzi, jj, half, DHID);
        __syncthreads();     // prior readers of s_r done before overwrite
#pragma unroll
        for (int i = 0; i < 16; i++) {
            float lo, hi;
            upk2(acc[0][i], lo, hi);
            float2 h = h2f[i0 + i]; h.x += lo; h.y += hi; h2f[i0 + i] = h;
            r2f[i0 + i] = make_float2(fmaxf(h.x, 0.f), fmaxf(h.y, 0.f));
            upk2(acc[1][i], lo, hi);
            h = h2f[i1 + i]; h.x += lo; h.y += hi; h2f[i1 + i] = h;
            r2f[i1 + i] = make_float2(fmaxf(h.x, 0.f), fmaxf(h.y, 0.f));
        }
        __syncthreads();

        // net = relu(h) @ W0 + b0 ; r = relu(net)
        bb0 = pk2(b0i[jj]); bb1 = pk2(b0i[jj + 64]);
#pragma unroll
        for (int i = 0; i < 16; i++) { acc[0][i] = bb0; acc[1][i] = bb1; }
        mm2(acc, r2, W0i, jj, half, DHID);
        __syncthreads();
#pragma unroll
        for (int i = 0; i < 16; i++) {
            float lo, hi;
            upk2(acc[0][i], lo, hi);
            r2f[i0 + i] = make_float2(fmaxf(lo, 0.f), fmaxf(hi, 0.f));
            upk2(acc[1][i], lo, hi);
            r2f[i1 + i] = make_float2(fmaxf(lo, 0.f), fmaxf(hi, 0.f));
        }
        __syncthreads();

        // h += relu(net) @ W1 + b1
        bb0 = pk2(b1i[jj]); bb1 = pk2(b1i[jj + 64]);
#pragma unroll
        for (int i = 0; i < 16; i++) { acc[0][i] = bb0; acc[1][i] = bb1; }
        mm2(acc, r2, W1i, jj, half, DHID);
        __syncthreads();
#pragma unroll
        for (int i = 0; i < 16; i++) {
            float lo, hi;
            upk2(acc[0][i], lo, hi);
            float2 h = h2f[i0 + i]; h.x += lo; h.y += hi; h2f[i0 + i] = h;
            if (blk == 2) r2f[i0 + i] = make_float2(fmaxf(h.x, 0.f), fmaxf(h.y, 0.f));
            upk2(acc[1][i], lo, hi);
            h = h2f[i1 + i]; h.x += lo; h.y += hi; h2f[i1 + i] = h;
            if (blk == 2) r2f[i1 + i] = make_float2(fmaxf(h.x, 0.f), fmaxf(h.y, 0.f));
        }
        __syncthreads();
    }

    // out = relu(h) @ Wout + bout
    for (int t = j; t < PP * DOUT; t += 128) {
        int p = t / DOUT, o = t - p * DOUT;
        float a = bout[o];
#pragma unroll 8
        for (int k = 0; k < DHID; k++) a += s_r[k * RSF + p] * Wout[k * DOUT + o];
        (GAUSS ? g_outg : g_outm)[(n0 + p) * DOUT + o] = a;
    }
}

// ---- 4) gaussian params + depth samples + per-ray sort ----
__global__ void gprep_kernel() {
    int r = blockIdx.x * blockDim.x + threadIdx.x;
    if (r >= NRAYS) return;
    float m[NG], sd[NG], d[SMAIN];
#pragma unroll
    for (int g = 0; g < NG; g++) {
        float o0 = g_outg[(r * NG + g) * 2], o1 = g_outg[(r * NG + g) * 2 + 1];
        m[g] = ((float)g + 0.5f) * 25.f + tanhf(o0) * 12.5f;
        sd[g] = 1.f / (1.f + expf(-o1)) * 5.f + 0.001f;
        g_means[r * NG + g] = m[g]; g_stds[r * NG + g] = sd[g];
    }
    for (int i = 0; i < 32; i++) d[i] = 0.5f + (float)i * (99.5f / 31.f);
    int idx = 32;
    for (int g = 0; g < NG; g++)
        for (int jj = 0; jj < 8; jj++)
            d[idx++] = m[g] + (-1.f + (float)jj * (2.f / 7.f)) * 2.f * sd[g];
    for (int i = 0; i < SMAIN; i++) d[i] = fminf(fmaxf(d[i], 0.01f), 100.f);
    for (int i = 1; i < SMAIN; i++) {
        float v = d[i]; int k = i - 1;
        while (k >= 0 && d[k] > v) { d[k + 1] = d[k]; k--; }
        d[k + 1] = v;
    }
    for (int i = 0; i < SMAIN; i++) g_dall[r * SMAIN + i] = d[i];
}

// ---- 5) rendering + losses ----
__device__ __forceinline__ void samp_img(const float *__restrict__ img,
                                         float u, float v, float *o3) {
    float x0f = fminf(fmaxf(floorf(u), 0.f), (float)(IMGW - 2));
    float y0f = fminf(fmaxf(floorf(v), 0.f), (float)(IMGH - 2));
    int x0 = (int)x0f, y0 = (int)y0f;
    float fx = fminf(fmaxf(u - x0f, 0.f), 1.f), fy = fminf(fmaxf(v - y0f, 0.f), 1.f);
    float w00 = (1.f - fx) * (1.f - fy), w10 = fx * (1.f - fy);
    float w01 = (1.f - fx) * fy, w11 = fx * fy;
#pragma unroll
    for (int c = 0; c < 3; c++) {
        int b = c * IMGH * IMGW + y0 * IMGW + x0;
        o3[c] = img[b] * w00 + img[b + 1] * w10 + img[b + IMGW] * w01 + img[b + IMGW + 1] * w11;
    }
}

__global__ void render_kernel(const float *__restrict__ src, const float *__restrict__ tgt,
                              const float *__restrict__ K4, const float *__restrict__ s2t,
                              const float *__restrict__ pix, float *__restrict__ dout) {
    int r = blockIdx.x * blockDim.x + threadIdx.x;
    if (r >= NRAYS) return;
    const float EPSf = 1e-6f;
    float d[SMAIN], w[SMAIN], q[SMAIN];
    for (int s = 0; s < SMAIN; s++) d[s] = g_dall[r * SMAIN + s];
    float T = 1.f, depth = 0.f, c0 = 0.f, c1 = 0.f, c2 = 0.f, wsum = 0.f;
    for (int s = 0; s < SMAIN; s++) {
        float4 o = reinterpret_cast<const float4 *>(g_outm)[r * SMAIN + s];
        float delta = (s < SMAIN - 1) ? (d[s + 1] - d[s]) : 1e10f;
        float alpha = 1.f - expf(-fmaxf(o.x, 0.f) * delta);
        float ww = alpha * T;
        T *= (1.f - alpha + 1e-10f);
        w[s] = ww; wsum += ww; depth += ww * d[s];
        c0 += ww / (1.f + expf(-o.y));
        c1 += ww / (1.f + expf(-o.z));
        c2 += ww / (1.f + expf(-o.w));
    }
    float m[NG], sd[NG], ls[NG];
#pragma unroll
    for (int g = 0; g < NG; g++) {
        m[g] = g_means[r * NG + g]; sd[g] = g_stds[r * NG + g]; ls[g] = logf(sd[g]);
    }
    float qsum = 0.f;
    for (int s = 0; s < SMAIN; s++) {
        float qq = 0.f;
#pragma unroll
        for (int g = 0; g < NG; g++) {
            float t = (d[s] - m[g]) / sd[g];
            qq += expf(-0.5f * t * t - ls[g]);
        }
        q[s] = qq * 0.25f; qsum += q[s];
    }
    float kl = 0.f;
    for (int s = 0; s < SMAIN; s++) {
        float pw = w[s] / (wsum + EPSf), qn = q[s] / (qsum + EPSf);
        kl += pw * (logf(pw + EPSf) - logf(qn + EPSf));
    }
    float d2c = 1e30f;
#pragma unroll
    for (int g = 0; g < NG; g++) d2c = fminf(d2c, fabsf(m[g] - depth));

    float sc[3]; samp_img(src, pix[2 * r], pix[2 * r + 1], sc);
    float closs = fabsf(sc[0] - c0) + fabsf(sc[1] - c1) + fabsf(sc[2] - c2);

    float cx = g_cam[3 * r] * depth, cy = g_cam[3 * r + 1] * depth, cz = g_cam[3 * r + 2] * depth;
    float tx = s2t[0] * cx + s2t[1] * cy + s2t[2]  * cz + s2t[3];
    float ty = s2t[4] * cx + s2t[5] * cy + s2t[6]  * cz + s2t[7];
    float tz = s2t[8] * cx + s2t[9] * cy + s2t[10] * cz + s2t[11];
    float pxp = K4[0] * tx + K4[1] * ty + K4[2] * tz;
    float pyp = K4[3] * tx + K4[4] * ty + K4[5] * tz;
    float pzp = K4[6] * tx + K4[7] * ty + K4[8] * tz;
    float tc[3]; samp_img(tgt, pxp / (pzp + EPSf), pyp / (pzp + EPSf), tc);
    float mask = (depth < 30.f) ? 1.f : 0.f;
    g_kl[r] = kl; g_d2c[r] = d2c; g_colL[r] = closs;
    g_rn[r] = mask * (fabsf(tc[0] - sc[0]) + fabsf(tc[1] - sc[1]) + fabsf(tc[2] - sc[2])) * (1.f / 3.f);
    g_rd[r] = mask;
    dout[1 + r] = depth;
    dout[1 + NRAYS + 3 * r + 0] = c0;
    dout[1 + NRAYS + 3 * r + 1] = c1;
    dout[1 + NRAYS + 3 * r + 2] = c2;
}

// ---- 6) deterministic scalar reduction ----
__global__ void reduce_kernel(float *__restrict__ dout) {
    __shared__ float sm[5][256];
    int t = threadIdx.x;
    float a[5] = {0, 0, 0, 0, 0};
    for (int r = t; r < NRAYS; r += 256) {
        a[0] += g_kl[r]; a[1] += g_d2c[r]; a[2] += g_colL[r]; a[3] += g_rn[r]; a[4] += g_rd[r];
    }
    for (int c = 0; c < 5; c++) sm[c][t] = a[c];
    __syncthreads();
    for (int s = 128; s > 0; s >>= 1) {
        if (t < s) for (int c = 0; c < 5; c++) sm[c][t] += sm[c][t + s];
        __syncthreads();
    }
    if (t == 0)
        dout[0] = sm[0][0] * (1.f / NRAYS) + 0.01f * sm[1][0] * (1.f / NRAYS) +
                  sm[2][0] * (1.f / (3.f * NRAYS)) + sm[3][0] / (sm[4][0] + 1e-6f);
}

extern "C" void kernel_launch(void* const* d_in, const int* in_sizes, int n_in,
                              void* d_out, int out_size) {
    const float *bev = (const float *)d_in[0];
    const float *src = (const float *)d_in[1];
    const float *tgt = (const float *)d_in[2];
    const float *K4  = (const float *)d_in[3];
    const float *s2i = (const float *)d_in[4];
    const float *s2t = (const float *)d_in[5];
    const float *pix = (const float *)d_in[6];
    const float *const *m1 = (const float *const *)&d_in[7];   // main MLP (4 out)
    const float *const *m2 = (const float *const *)&d_in[17];  // gauss MLP (2 out)
    float *dout = (float *)d_out;

    int smem = 3 * 128 * RSF * 4;   // 104448 B
    cudaFuncSetAttribute(decode_kernel<true>,  cudaFuncAttributeMaxDynamicSharedMemorySize, smem);
    cudaFuncSetAttribute(decode_kernel<false>, cudaFuncAttributeMaxDynamicSharedMemorySize, smem);

    transpose_kernel<<<dim3(7, 4, 1600), dim3(32, 8)>>>(bev);
    setup_kernel<<<32, 128>>>(K4, s2i, pix);
    decode_kernel<true><<<NRAYS * NG / PP, 128, smem>>>(
        s2i, m2[0], m2[1], m2[2], m2[3], m2[4], m2[5], m2[6], m2[7], m2[8], m2[9]);
    gprep_kernel<<<64, 64>>>();
    decode_kernel<false><<<NRAYS * SMAIN / PP, 128, smem>>>(
        s2i, m1[0], m1[1], m1[2], m1[3], m1[4], m1[5], m1[6], m1[7], m1[8], m1[9]);
    render_kernel<<<64, 64>>>(src, tgt, K4, s2t, pix, dout);
    reduce_kernel<<<1, 256>>>(dout);
}

// round 11
// speedup vs baseline: 1.0824x; 1.0496x over previous
#include <cuda_runtime.h>

typedef unsigned long long u64;

#define NRAYS 4096
#define SMAIN 64
#define NG    4
#define DHID  128
#define IMGH  900
#define IMGW  1600

// ---- device scratch (no cudaMalloc allowed) ----
__device__ __align__(16) float g_vox[8 * 200 * 200 * 128];
__device__ float g_dirs[NRAYS * 3], g_view[NRAYS * 3], g_cam[NRAYS * 3];
__device__ float g_outg[NRAYS * NG * 2];
__device__ float g_means[NRAYS * NG], g_stds[NRAYS * NG];
__device__ float g_dall[NRAYS * SMAIN];
__device__ __align__(16) float g_outm[NRAYS * SMAIN * 4];
__device__ float g_kl[NRAYS], g_d2c[NRAYS], g_colL[NRAYS], g_rn[NRAYS], g_rd[NRAYS];

// ---- f32x2 helpers ----
__device__ __forceinline__ u64 pk2(float v) {
    u64 r; asm("mov.b64 %0, {%1, %1};" : "=l"(r) : "f"(v)); return r;
}
__device__ __forceinline__ void fma2(u64 &d, u64 a, u64 b) {
    asm("fma.rn.f32x2 %0, %1, %2, %0;" : "+l"(d) : "l"(a), "l"(b));
}
__device__ __forceinline__ void upk2(u64 v, float &lo, float &hi) {
    asm("mov.b64 {%0, %1}, %2;" : "=f"(lo), "=f"(hi) : "l"(v));
}

constexpr int PP   = 64;          // points per decode block
constexpr int RSU  = 34;          // activation row stride (u64)
constexpr int RSF  = 68;          // activation row stride (floats)
constexpr int WBUF = 64 * 128;    // floats per weight staging buffer (32 KB)

// cp.async weight prefetch: bytes must be multiple of 16; 256 threads
__device__ __forceinline__ void pf(float *sdst, const float *g, int bytes, int j) {
    unsigned sa = (unsigned)__cvta_generic_to_shared(sdst);
    for (int off = j * 16; off < bytes; off += 256 * 16)
        asm volatile("cp.async.cg.shared.global [%0], [%1], 16;"
                     :: "r"(sa + off), "l"((const char *)g + off));
    asm volatile("cp.async.commit_group;" ::: "memory");
}
#define BND() { asm volatile("cp.async.wait_group 0;" ::: "memory"); __syncthreads(); }

// matmul over ROWS k-rows: weights from smem (stride-1 LDS), activations broadcast LDS.128
template <int ROWS>
__device__ __forceinline__ void mmW(u64 acc[16], const u64 *__restrict__ act,
                                    const float *__restrict__ w, int jj, int half) {
#pragma unroll 2
    for (int k = 0; k < ROWS; k++) {
        u64 wv = pk2(w[k * 128 + jj]);
        const ulonglong2 *s = (const ulonglong2 *)(act + k * RSU + half * 16);
#pragma unroll
        for (int i = 0; i < 8; i++) {
            ulonglong2 v = s[i];
            fma2(acc[2 * i],     v.x, wv);
            fma2(acc[2 * i + 1], v.y, wv);
        }
    }
}

// ---- 1) bev (1,1024,200,200) -> vox (8,200,200,128) ----
__global__ void transpose_kernel(const float *__restrict__ bev) {
    __shared__ float tile[32][33];
    int dh = blockIdx.z, d = dh / 200, h = dh - d * 200;
    int w0 = blockIdx.x * 32, c0 = blockIdx.y * 32;
    int tx = threadIdx.x, ty = threadIdx.y;
#pragma unroll
    for (int i = 0; i < 32; i += 8) {
        int c = c0 + ty + i, w = w0 + tx;
        if (w < 200) tile[ty + i][tx] = bev[(c * 8 + d) * 40000 + h * 200 + w];
    }
    __syncthreads();
#pragma unroll
    for (int i = 0; i < 32; i += 8) {
        int w = w0 + ty + i, c = c0 + tx;
        if (w < 200) g_vox[((d * 200 + h) * 200 + w) * 128 + c] = tile[tx][ty + i];
    }
}

// ---- 2) per-ray setup ----
__global__ void setup_kernel(const float *__restrict__ K4,
                             const float *__restrict__ s2i,
                             const float *__restrict__ pix) {
    int r = blockIdx.x * blockDim.x + threadIdx.x;
    if (r >= NRAYS) return;
    float a = K4[0], b = K4[1], c = K4[2], d = K4[3], e = K4[4], f = K4[5];
    float g = K4[6], h = K4[7], i9 = K4[8];
    float A = e * i9 - f * h, B = c * h - b * i9, C = b * f - c * e;
    float D = f * g - d * i9, E = a * i9 - c * g, F = c * d - a * f;
    float G = d * h - e * g, H = b * g - a * h, I = a * e - b * d;
    float idet = 1.f / (a * A + b * D + c * G);
    float u = pix[2 * r], v = pix[2 * r + 1];
    float cx = (A * u + B * v + C) * idet;
    float cy = (D * u + E * v + F) * idet;
    float cz = (G * u + H * v + I) * idet;
    g_cam[3 * r] = cx; g_cam[3 * r + 1] = cy; g_cam[3 * r + 2] = cz;
    float dx = s2i[0] * cx + s2i[1] * cy + s2i[2]  * cz;
    float dy = s2i[4] * cx + s2i[5] * cy + s2i[6]  * cz;
    float dz = s2i[8] * cx + s2i[9] * cy + s2i[10] * cz;
    g_dirs[3 * r] = dx; g_dirs[3 * r + 1] = dy; g_dirs[3 * r + 2] = dz;
    float inv = rsqrtf(dx * dx + dy * dy + dz * dz);
    g_view[3 * r] = dx * inv; g_view[3 * r + 1] = dy * inv; g_view[3 * r + 2] = dz * inv;
}

// ---- 3) ResNet-MLP decode: smem-staged weights, f32x2 math ----
template <bool GAUSS>
__global__ void __launch_bounds__(256, 1) decode_kernel(
    const float *__restrict__ s2i,
    const float *__restrict__ Win, const float *__restrict__ bin,
    const float *__restrict__ Wz,  const float *__restrict__ bz,
    const float *__restrict__ W0,  const float *__restrict__ b0,
    const float *__restrict__ W1,  const float *__restrict__ b1,
    const float *__restrict__ Wout,const float *__restrict__ bout)
{
    constexpr int S = GAUSS ? NG : SMAIN;
    constexpr int DOUT = GAUSS ? 2 : 4;
    extern __shared__ float sm[];
    float *s_r = sm;                    // overlays s_x
    float *s_x = sm;
    float *s_z = sm + 128 * RSF;
    float *s_h = s_z + 128 * RSF;
    float *s_w = s_h + 128 * RSF;       // 2 * WBUF floats
    __shared__ float s_pt[PP][3], s_vd[PP][3], s_f[PP][3];
    __shared__ int   s_base[PP], s_val[PP];

    const int j = threadIdx.x;          // 0..255
    const int jj = j & 127, half = j >> 7;
    const int n0 = blockIdx.x * PP;

    pf(s_w, Win, 42 * 512, j);          // chunk0 -> buf0 (overlaps geometry)

    if (j < PP) {
        int n = n0 + j, r = n / S, s = n - r * S;
        float dpt = GAUSS ? ((float)s + 0.5f) * 25.0f : g_dall[n];
        float px = s2i[3]  + g_dirs[3 * r]     * dpt;
        float py = s2i[7]  + g_dirs[3 * r + 1] * dpt;
        float pz = s2i[11] + g_dirs[3 * r + 2] * dpt;
        s_pt[j][0] = px; s_pt[j][1] = py; s_pt[j][2] = pz;
        s_vd[j][0] = g_view[3 * r]; s_vd[j][1] = g_view[3 * r + 1]; s_vd[j][2] = g_view[3 * r + 2];
        float gx = (px + 51.2f) * (199.0f / 102.4f);
        float gy = (py + 51.2f) * (199.0f / 102.4f);
        float gz = (pz + 5.0f) * (7.0f / 8.0f);
        s_val[j] = (gx >= 0.f) & (gx <= 199.f) & (gy >= 0.f) & (gy <= 199.f) &
                   (gz >= 0.f) & (gz <= 7.f);
        int x0 = min(max((int)floorf(gx), 0), 198);
        int y0 = min(max((int)floorf(gy), 0), 198);
        int z0 = min(max((int)floorf(gz), 0), 6);
        s_f[j][0] = fminf(fmaxf(gx - (float)x0, 0.f), 1.f);
        s_f[j][1] = fminf(fmaxf(gy - (float)y0, 0.f), 1.f);
        s_f[j][2] = fminf(fmaxf(gz - (float)z0, 0.f), 1.f);
        s_base[j] = ((z0 * 200 + x0) * 200 + y0) * 128;
    }
    __syncthreads();

    if (j < 42) {   // pos-enc features, layout [feature][point]
#pragma unroll 4
        for (int p = 0; p < PP; p++) {
            float v;
            if (j < 3) v = s_pt[p][j];
            else if (j < 39) {
                int q = j - 3, f = q / 6, t = q - f * 6;
                float fr = 3.14159265358979323846f * (float)(1 << f);
                float xx = ((t < 3) ? s_pt[p][t] : s_pt[p][t - 3]) * fr;
                v = (t < 3) ? sinf(xx) : cosf(xx);
            } else v = s_vd[p][j - 39];
            s_x[j * RSF + p] = v;
        }
    }
    {   // trilinear gather: channel jj, points split by half
        int p0 = half * 32;
#pragma unroll 2
        for (int p = p0; p < p0 + 32; p++) {
            float zv = 0.f;
            if (s_val[p]) {
                const float *vp = g_vox + s_base[p] + jj;
                float fx = s_f[p][0], fy = s_f[p][1], fz = s_f[p][2];
                float ox = 1.f - fx, oy = 1.f - fy, oz = 1.f - fz;
                float c00 = vp[0]       * ox + vp[25600]   * fx;
                float c01 = vp[128]     * ox + vp[25728]   * fx;
                float c10 = vp[5120000] * ox + vp[5145600] * fx;
                float c11 = vp[5120128] * ox + vp[5145728] * fx;
                zv = (c00 * oy + c01 * fy) * oz + (c10 * oy + c11 * fy) * fz;
            }
            s_z[jj * RSF + p] = zv;
        }
    }

    const u64 *x2 = (const u64 *)s_x;
    const u64 *z2 = (const u64 *)s_z;
    const u64 *r2 = (const u64 *)s_r;
    u64    *h2u = (u64 *)s_h;
    float2 *h2f = (float2 *)s_h;
    float2 *r2f = (float2 *)s_r;
    const int i0 = jj * RSU + half * 16;
    u64 acc[16];

    // ---- input matmul: h = x @ Win + bin  (chunk0 in buf0) ----
    BND();
    pf(s_w + WBUF, Wz, 64 * 512, j);              // Wz blk0 lo -> buf1
    {
        u64 bb = pk2(bin[jj]);
#pragma unroll
        for (int i = 0; i < 16; i++) acc[i] = bb;
        mmW<42>(acc, x2, s_w, jj, half);
#pragma unroll
        for (int i = 0; i < 16; i++) h2u[i0 + i] = acc[i];
    }

    // chunk parity: every matmul in the blk loop is lo->buf1, hi->buf0
    for (int blk = 0; blk < 3; blk++) {
        const float *Wzi = Wz + blk * 16384, *bzi = bz + blk * 128;
        const float *W0i = W0 + blk * 16384, *b0i = b0 + blk * 128;
        const float *W1i = W1 + blk * 16384, *b1i = b1 + blk * 128;

        // -- h += z @ Wz + bz ; r = relu(h) --
        BND();
        pf(s_w, Wzi + 64 * 128, 64 * 512, j);     // Wz hi -> buf0
        u64 bb = pk2(bzi[jj]);
#pragma unroll
        for (int i = 0; i < 16; i++) acc[i] = bb;
        mmW<64>(acc, z2, s_w + WBUF, jj, half);
        BND();
        pf(s_w + WBUF, W0i, 64 * 512, j);         // W0 lo -> buf1
        mmW<64>(acc, z2 + 64 * RSU, s_w, jj, half);
#pragma unroll
        for (int i = 0; i < 16; i++) {            // writes h,r; disjoint from z/w
            float lo, hi; upk2(acc[i], lo, hi);
            float2 h = h2f[i0 + i]; h.x += lo; h.y += hi; h2f[i0 + i] = h;
            r2f[i0 + i] = make_float2(fmaxf(h.x, 0.f), fmaxf(h.y, 0.f));
        }

        // -- net = relu(h) @ W0 + b0 ; r = relu(net) --
        BND();                                     // publishes r
        pf(s_w, W0i + 64 * 128, 64 * 512, j);     // W0 hi -> buf0
        bb = pk2(b0i[jj]);
#pragma unroll
        for (int i = 0; i < 16; i++) acc[i] = bb;
        mmW<64>(acc, r2, s_w + WBUF, jj, half);
        BND();
        pf(s_w + WBUF, W1i, 64 * 512, j);         // W1 lo -> buf1
        mmW<64>(acc, r2 + 64 * RSU, s_w, jj, half);
        __syncthreads();                           // r readers done before overwrite
#pragma unroll
        for (int i = 0; i < 16; i++) {
            float lo, hi; upk2(acc[i], lo, hi);
            r2f[i0 + i] = make_float2(fmaxf(lo, 0.f), fmaxf(hi, 0.f));
        }

        // -- h += relu(net) @ W1 + b1 --
        BND();                                     // publishes r
        pf(s_w, W1i + 64 * 128, 64 * 512, j);     // W1 hi -> buf0
        bb = pk2(b1i[jj]);
#pragma unroll
        for (int i = 0; i < 16; i++) acc[i] = bb;
        mmW<64>(acc, r2, s_w + WBUF, jj, half);
        BND();
        if (blk < 2) pf(s_w + WBUF, Wzi + 16384, 64 * 512, j);  // next blk's Wz lo -> buf1 (FIXED)
        mmW<64>(acc, r2 + 64 * RSU, s_w, jj, half);
        __syncthreads();                           // r readers done before overwrite
#pragma unroll
        for (int i = 0; i < 16; i++) {
            float lo, hi; upk2(acc[i], lo, hi);
            float2 h = h2f[i0 + i]; h.x += lo; h.y += hi; h2f[i0 + i] = h;
            if (blk == 2) r2f[i0 + i] = make_float2(fmaxf(h.x, 0.f), fmaxf(h.y, 0.f));
        }
    }
    __syncthreads();

    // out = relu(h) @ Wout + bout  (Wout tiny: L1-resident LDG)
    if (j < PP * DOUT) {
        int p = j / DOUT, o = j - p * DOUT;
        float a = bout[o];
#pragma unroll 8
        for (int k = 0; k < DHID; k++) a += s_r[k * RSF + p] * Wout[k * DOUT + o];
        (GAUSS ? g_outg : g_outm)[(n0 + p) * DOUT + o] = a;
    }
}

// ---- 4) gaussian params + depth samples + per-ray sort ----
__global__ void gprep_kernel() {
    int r = blockIdx.x * blockDim.x + threadIdx.x;
    if (r >= NRAYS) return;
    float m[NG], sd[NG], d[SMAIN];
#pragma unroll
    for (int g = 0; g < NG; g++) {
        float o0 = g_outg[(r * NG + g) * 2], o1 = g_outg[(r * NG + g) * 2 + 1];
        m[g] = ((float)g + 0.5f) * 25.f + tanhf(o0) * 12.5f;
        sd[g] = 1.f / (1.f + expf(-o1)) * 5.f + 0.001f;
        g_means[r * NG + g] = m[g]; g_stds[r * NG + g] = sd[g];
    }
    for (int i = 0; i < 32; i++) d[i] = 0.5f + (float)i * (99.5f / 31.f);
    int idx = 32;
    for (int g = 0; g < NG; g++)
        for (int jj = 0; jj < 8; jj++)
            d[idx++] = m[g] + (-1.f + (float)jj * (2.f / 7.f)) * 2.f * sd[g];
    for (int i = 0; i < SMAIN; i++) d[i] = fminf(fmaxf(d[i], 0.01f), 100.f);
    for (int i = 1; i < SMAIN; i++) {
        float v = d[i]; int k = i - 1;
        while (k >= 0 && d[k] > v) { d[k + 1] = d[k]; k--; }
        d[k + 1] = v;
    }
    for (int i = 0; i < SMAIN; i++) g_dall[r * SMAIN + i] = d[i];
}

// ---- 5) rendering + losses ----
__device__ __forceinline__ void samp_img(const float *__restrict__ img,
                                         float u, float v, float *o3) {
    float x0f = fminf(fmaxf(floorf(u), 0.f), (float)(IMGW - 2));
    float y0f = fminf(fmaxf(floorf(v), 0.f), (float)(IMGH - 2));
    int x0 = (int)x0f, y0 = (int)y0f;
    float fx = fminf(fmaxf(u - x0f, 0.f), 1.f), fy = fminf(fmaxf(v - y0f, 0.f), 1.f);
    float w00 = (1.f - fx) * (1.f - fy), w10 = fx * (1.f - fy);
    float w01 = (1.f - fx) * fy, w11 = fx * fy;
#pragma unroll
    for (int c = 0; c < 3; c++) {
        int b = c * IMGH * IMGW + y0 * IMGW + x0;
        o3[c] = img[b] * w00 + img[b + 1] * w10 + img[b + IMGW] * w01 + img[b + IMGW + 1] * w11;
    }
}

__global__ void render_kernel(const float *__restrict__ src, const float *__restrict__ tgt,
                              const float *__restrict__ K4, const float *__restrict__ s2t,
                              const float *__restrict__ pix, float *__restrict__ dout) {
    int r = blockIdx.x * blockDim.x + threadIdx.x;
    if (r >= NRAYS) return;
    const float EPSf = 1e-6f;
    float d[SMAIN], w[SMAIN], q[SMAIN];
    for (int s = 0; s < SMAIN; s++) d[s] = g_dall[r * SMAIN + s];
    float T = 1.f, depth = 0.f, c0 = 0.f, c1 = 0.f, c2 = 0.f, wsum = 0.f;
    for (int s = 0; s < SMAIN; s++) {
        float4 o = reinterpret_cast<const float4 *>(g_outm)[r * SMAIN + s];
        float delta = (s < SMAIN - 1) ? (d[s + 1] - d[s]) : 1e10f;
        float alpha = 1.f - expf(-fmaxf(o.x, 0.f) * delta);
        float ww = alpha * T;
        T *= (1.f - alpha + 1e-10f);
        w[s] = ww; wsum += ww; depth += ww * d[s];
        c0 += ww / (1.f + expf(-o.y));
        c1 += ww / (1.f + expf(-o.z));
        c2 += ww / (1.f + expf(-o.w));
    }
    float m[NG], sd[NG], ls[NG];
#pragma unroll
    for (int g = 0; g < NG; g++) {
        m[g] = g_means[r * NG + g]; sd[g] = g_stds[r * NG + g]; ls[g] = logf(sd[g]);
    }
    float qsum = 0.f;
    for (int s = 0; s < SMAIN; s++) {
        float qq = 0.f;
#pragma unroll
        for (int g = 0; g < NG; g++) {
            float t = (d[s] - m[g]) / sd[g];
            qq += expf(-0.5f * t * t - ls[g]);
        }
        q[s] = qq * 0.25f; qsum += q[s];
    }
    float kl = 0.f;
    for (int s = 0; s < SMAIN; s++) {
        float pw = w[s] / (wsum + EPSf), qn = q[s] / (qsum + EPSf);
        kl += pw * (logf(pw + EPSf) - logf(qn + EPSf));
    }
    float d2c = 1e30f;
#pragma unroll
    for (int g = 0; g < NG; g++) d2c = fminf(d2c, fabsf(m[g] - depth));

    float sc[3]; samp_img(src, pix[2 * r], pix[2 * r + 1], sc);
    float closs = fabsf(sc[0] - c0) + fabsf(sc[1] - c1) + fabsf(sc[2] - c2);

    float cx = g_cam[3 * r] * depth, cy = g_cam[3 * r + 1] * depth, cz = g_cam[3 * r + 2] * depth;
    float tx = s2t[0] * cx + s2t[1] * cy + s2t[2]  * cz + s2t[3];
    float ty = s2t[4] * cx + s2t[5] * cy + s2t[6]  * cz + s2t[7];
    float tz = s2t[8] * cx + s2t[9] * cy + s2t[10] * cz + s2t[11];
    float pxp = K4[0] * tx + K4[1] * ty + K4[2] * tz;
    float pyp = K4[3] * tx + K4[4] * ty + K4[5] * tz;
    float pzp = K4[6] * tx + K4[7] * ty + K4[8] * tz;
    float tc[3]; samp_img(tgt, pxp / (pzp + EPSf), pyp / (pzp + EPSf), tc);
    float mask = (depth < 30.f) ? 1.f : 0.f;
    g_kl[r] = kl; g_d2c[r] = d2c; g_colL[r] = closs;
    g_rn[r] = mask * (fabsf(tc[0] - sc[0]) + fabsf(tc[1] - sc[1]) + fabsf(tc[2] - sc[2])) * (1.f / 3.f);
    g_rd[r] = mask;
    dout[1 + r] = depth;
    dout[1 + NRAYS + 3 * r + 0] = c0;
    dout[1 + NRAYS + 3 * r + 1] = c1;
    dout[1 + NRAYS + 3 * r + 2] = c2;
}

// ---- 6) deterministic scalar reduction ----
__global__ void reduce_kernel(float *__restrict__ dout) {
    __shared__ float sm[5][256];
    int t = threadIdx.x;
    float a[5] = {0, 0, 0, 0, 0};
    for (int r = t; r < NRAYS; r += 256) {
        a[0] += g_kl[r]; a[1] += g_d2c[r]; a[2] += g_colL[r]; a[3] += g_rn[r]; a[4] += g_rd[r];
    }
    for (int c = 0; c < 5; c++) sm[c][t] = a[c];
    __syncthreads();
    for (int s = 128; s > 0; s >>= 1) {
        if (t < s) for (int c = 0; c < 5; c++) sm[c][t] += sm[c][t + s];
        __syncthreads();
    }
    if (t == 0)
        dout[0] = sm[0][0] * (1.f / NRAYS) + 0.01f * sm[1][0] * (1.f / NRAYS) +
                  sm[2][0] * (1.f / (3.f * NRAYS)) + sm[3][0] / (sm[4][0] + 1e-6f);
}

extern "C" void kernel_launch(void* const* d_in, const int* in_sizes, int n_in,
                              void* d_out, int out_size) {
    const float *bev = (const float *)d_in[0];
    const float *src = (const float *)d_in[1];
    const float *tgt = (const float *)d_in[2];
    const float *K4  = (const float *)d_in[3];
    const float *s2i = (const float *)d_in[4];
    const float *s2t = (const float *)d_in[5];
    const float *pix = (const float *)d_in[6];
    const float *const *m1 = (const float *const *)&d_in[7];   // main MLP (4 out)
    const float *const *m2 = (const float *const *)&d_in[17];  // gauss MLP (2 out)
    float *dout = (float *)d_out;

    int smem = (3 * 128 * RSF + 2 * WBUF) * 4;   // 169984 B
    cudaFuncSetAttribute(decode_kernel<true>,  cudaFuncAttributeMaxDynamicSharedMemorySize, smem);
    cudaFuncSetAttribute(decode_kernel<false>, cudaFuncAttributeMaxDynamicSharedMemorySize, smem);

    transpose_kernel<<<dim3(7, 4, 1600), dim3(32, 8)>>>(bev);
    setup_kernel<<<32, 128>>>(K4, s2i, pix);
    decode_kernel<true><<<NRAYS * NG / PP, 256, smem>>>(
        s2i, m2[0], m2[1], m2[2], m2[3], m2[4], m2[5], m2[6], m2[7], m2[8], m2[9]);
    gprep_kernel<<<64, 64>>>();
    decode_kernel<false><<<NRAYS * SMAIN / PP, 256, smem>>>(
        s2i, m1[0], m1[1], m1[2], m1[3], m1[4], m1[5], m1[6], m1[7], m1[8], m1[9]);
    render_kernel<<<64, 64>>>(src, tgt, K4, s2t, pix, dout);
    reduce_kernel<<<1, 256>>>(dout);
}

// round 12
// speedup vs baseline: 1.0840x; 1.0015x over previous
#include <cuda_runtime.h>

typedef unsigned long long u64;

#define NRAYS 4096
#define SMAIN 64
#define NG    4
#define DHID  128
#define IMGH  900
#define IMGW  1600

// ---- device scratch (no cudaMalloc allowed) ----
__device__ __align__(16) float g_vox[8 * 200 * 200 * 128];
__device__ float g_dirs[NRAYS * 3], g_view[NRAYS * 3], g_cam[NRAYS * 3];
__device__ float g_outg[NRAYS * NG * 2];
__device__ float g_means[NRAYS * NG], g_stds[NRAYS * NG];
__device__ float g_dall[NRAYS * SMAIN];
__device__ __align__(16) float g_outm[NRAYS * SMAIN * 4];
__device__ float g_kl[NRAYS], g_d2c[NRAYS], g_colL[NRAYS], g_rn[NRAYS], g_rd[NRAYS];

// ---- f32x2 helpers ----
__device__ __forceinline__ u64 pk2(float v) {
    u64 r; asm("mov.b64 %0, {%1, %1};" : "=l"(r) : "f"(v)); return r;
}
__device__ __forceinline__ void fma2(u64 &d, u64 a, u64 b) {
    asm("fma.rn.f32x2 %0, %1, %2, %0;" : "+l"(d) : "l"(a), "l"(b));
}
__device__ __forceinline__ void upk2(u64 v, float &lo, float &hi) {
    asm("mov.b64 {%0, %1}, %2;" : "=f"(lo), "=f"(hi) : "l"(v));
}

constexpr int PP   = 64;          // points per decode block
constexpr int RSU  = 34;          // activation row stride (u64)
constexpr int RSF  = 68;          // activation row stride (floats)
constexpr int WBUF = 64 * 128;    // floats per weight staging buffer (32 KB)

// cp.async weight prefetch: bytes must be multiple of 16; 256 threads
__device__ __forceinline__ void pf(float *sdst, const float *g, int bytes, int j) {
    unsigned sa = (unsigned)__cvta_generic_to_shared(sdst);
    for (int off = j * 16; off < bytes; off += 256 * 16)
        asm volatile("cp.async.cg.shared.global [%0], [%1], 16;"
                     :: "r"(sa + off), "l"((const char *)g + off));
    asm volatile("cp.async.commit_group;" ::: "memory");
}
#define BND() { asm volatile("cp.async.wait_group 0;" ::: "memory"); __syncthreads(); }

// matmul over ROWS k-rows: weights from smem (stride-1 LDS), activations broadcast LDS.128
template <int ROWS>
__device__ __forceinline__ void mmW(u64 acc[16], const u64 *__restrict__ act,
                                    const float *__restrict__ w, int jj, int half) {
#pragma unroll 2
    for (int k = 0; k < ROWS; k++) {
        u64 wv = pk2(w[k * 128 + jj]);
        const ulonglong2 *s = (const ulonglong2 *)(act + k * RSU + half * 16);
#pragma unroll
        for (int i = 0; i < 8; i++) {
            ulonglong2 v = s[i];
            fma2(acc[2 * i],     v.x, wv);
            fma2(acc[2 * i + 1], v.y, wv);
        }
    }
}

// ---- 1) bev (1,1024,200,200) -> vox (8,200,200,128) ----
__global__ void transpose_kernel(const float *__restrict__ bev) {
    __shared__ float tile[32][33];
    int dh = blockIdx.z, d = dh / 200, h = dh - d * 200;
    int w0 = blockIdx.x * 32, c0 = blockIdx.y * 32;
    int tx = threadIdx.x, ty = threadIdx.y;
#pragma unroll
    for (int i = 0; i < 32; i += 8) {
        int c = c0 + ty + i, w = w0 + tx;
        if (w < 200) tile[ty + i][tx] = bev[(c * 8 + d) * 40000 + h * 200 + w];
    }
    __syncthreads();
#pragma unroll
    for (int i = 0; i < 32; i += 8) {
        int w = w0 + ty + i, c = c0 + tx;
        if (w < 200) g_vox[((d * 200 + h) * 200 + w) * 128 + c] = tile[tx][ty + i];
    }
}

// ---- 2) per-ray setup ----
__global__ void setup_kernel(const float *__restrict__ K4,
                             const float *__restrict__ s2i,
                             const float *__restrict__ pix) {
    int r = blockIdx.x * blockDim.x + threadIdx.x;
    if (r >= NRAYS) return;
    float a = K4[0], b = K4[1], c = K4[2], d = K4[3], e = K4[4], f = K4[5];
    float g = K4[6], h = K4[7], i9 = K4[8];
    float A = e * i9 - f * h, B = c * h - b * i9, C = b * f - c * e;
    float D = f * g - d * i9, E = a * i9 - c * g, F = c * d - a * f;
    float G = d * h - e * g, H = b * g - a * h, I = a * e - b * d;
    float idet = 1.f / (a * A + b * D + c * G);
    float u = pix[2 * r], v = pix[2 * r + 1];
    float cx = (A * u + B * v + C) * idet;
    float cy = (D * u + E * v + F) * idet;
    float cz = (G * u + H * v + I) * idet;
    g_cam[3 * r] = cx; g_cam[3 * r + 1] = cy; g_cam[3 * r + 2] = cz;
    float dx = s2i[0] * cx + s2i[1] * cy + s2i[2]  * cz;
    float dy = s2i[4] * cx + s2i[5] * cy + s2i[6]  * cz;
    float dz = s2i[8] * cx + s2i[9] * cy + s2i[10] * cz;
    g_dirs[3 * r] = dx; g_dirs[3 * r + 1] = dy; g_dirs[3 * r + 2] = dz;
    float inv = rsqrtf(dx * dx + dy * dy + dz * dz);
    g_view[3 * r] = dx * inv; g_view[3 * r + 1] = dy * inv; g_view[3 * r + 2] = dz * inv;
}

// ---- 3) ResNet-MLP decode: smem-staged weights, f32x2 math ----
template <bool GAUSS>
__global__ void __launch_bounds__(256, 1) decode_kernel(
    const float *__restrict__ s2i,
    const float *__restrict__ Win, const float *__restrict__ bin,
    const float *__restrict__ Wz,  const float *__restrict__ bz,
    const float *__restrict__ W0,  const float *__restrict__ b0,
    const float *__restrict__ W1,  const float *__restrict__ b1,
    const float *__restrict__ Wout,const float *__restrict__ bout)
{
    constexpr int S = GAUSS ? NG : SMAIN;
    constexpr int DOUT = GAUSS ? 2 : 4;
    extern __shared__ float sm[];
    float *s_r = sm;                    // overlays s_x
    float *s_x = sm;
    float *s_z = sm + 128 * RSF;
    float *s_h = s_z + 128 * RSF;
    float *s_w = s_h + 128 * RSF;       // 2 * WBUF floats
    __shared__ float s_pt[PP][3], s_vd[PP][3], s_f[PP][3];
    __shared__ int   s_base[PP], s_val[PP];

    const int j = threadIdx.x;          // 0..255
    const int jj = j & 127, half = j >> 7;
    const int n0 = blockIdx.x * PP;

    pf(s_w, Win, 42 * 512, j);          // chunk0 -> buf0 (overlaps geometry)

    if (j < PP) {
        int n = n0 + j, r = n / S, s = n - r * S;
        float dpt = GAUSS ? ((float)s + 0.5f) * 25.0f : g_dall[n];
        float px = s2i[3]  + g_dirs[3 * r]     * dpt;
        float py = s2i[7]  + g_dirs[3 * r + 1] * dpt;
        float pz = s2i[11] + g_dirs[3 * r + 2] * dpt;
        s_pt[j][0] = px; s_pt[j][1] = py; s_pt[j][2] = pz;
        s_vd[j][0] = g_view[3 * r]; s_vd[j][1] = g_view[3 * r + 1]; s_vd[j][2] = g_view[3 * r + 2];
        float gx = (px + 51.2f) * (199.0f / 102.4f);
        float gy = (py + 51.2f) * (199.0f / 102.4f);
        float gz = (pz + 5.0f) * (7.0f / 8.0f);
        s_val[j] = (gx >= 0.f) & (gx <= 199.f) & (gy >= 0.f) & (gy <= 199.f) &
                   (gz >= 0.f) & (gz <= 7.f);
        int x0 = min(max((int)floorf(gx), 0), 198);
        int y0 = min(max((int)floorf(gy), 0), 198);
        int z0 = min(max((int)floorf(gz), 0), 6);
        s_f[j][0] = fminf(fmaxf(gx - (float)x0, 0.f), 1.f);
        s_f[j][1] = fminf(fmaxf(gy - (float)y0, 0.f), 1.f);
        s_f[j][2] = fminf(fmaxf(gz - (float)z0, 0.f), 1.f);
        s_base[j] = ((z0 * 200 + x0) * 200 + y0) * 128;
    }
    __syncthreads();

    if (j < 42) {   // pos-enc features, layout [feature][point]
#pragma unroll 4
        for (int p = 0; p < PP; p++) {
            float v;
            if (j < 3) v = s_pt[p][j];
            else if (j < 39) {
                int q = j - 3, f = q / 6, t = q - f * 6;
                float fr = 3.14159265358979323846f * (float)(1 << f);
                float xx = ((t < 3) ? s_pt[p][t] : s_pt[p][t - 3]) * fr;
                v = (t < 3) ? sinf(xx) : cosf(xx);
            } else v = s_vd[p][j - 39];
            s_x[j * RSF + p] = v;
        }
    }
    {   // trilinear gather: channel jj, points split by half
        int p0 = half * 32;
#pragma unroll 2
        for (int p = p0; p < p0 + 32; p++) {
            float zv = 0.f;
            if (s_val[p]) {
                const float *vp = g_vox + s_base[p] + jj;
                float fx = s_f[p][0], fy = s_f[p][1], fz = s_f[p][2];
                float ox = 1.f - fx, oy = 1.f - fy, oz = 1.f - fz;
                float c00 = vp[0]       * ox + vp[25600]   * fx;
                float c01 = vp[128]     * ox + vp[25728]   * fx;
                float c10 = vp[5120000] * ox + vp[5145600] * fx;
                float c11 = vp[5120128] * ox + vp[5145728] * fx;
                zv = (c00 * oy + c01 * fy) * oz + (c10 * oy + c11 * fy) * fz;
            }
            s_z[jj * RSF + p] = zv;
        }
    }

    const u64 *x2 = (const u64 *)s_x;
    const u64 *z2 = (const u64 *)s_z;
    const u64 *r2 = (const u64 *)s_r;
    u64    *h2u = (u64 *)s_h;
    float2 *h2f = (float2 *)s_h;
    float2 *r2f = (float2 *)s_r;
    const int i0 = jj * RSU + half * 16;
    u64 acc[16];

    // ---- input matmul: h = x @ Win + bin  (chunk0 in buf0) ----
    BND();
    pf(s_w + WBUF, Wz, 64 * 512, j);              // Wz blk0 lo -> buf1
    {
        u64 bb = pk2(bin[jj]);
#pragma unroll
        for (int i = 0; i < 16; i++) acc[i] = bb;
        mmW<42>(acc, x2, s_w, jj, half);
#pragma unroll
        for (int i = 0; i < 16; i++) h2u[i0 + i] = acc[i];
    }

    // chunk parity: every matmul in the blk loop is lo->buf1, hi->buf0
    for (int blk = 0; blk < 3; blk++) {
        const float *Wzi = Wz + blk * 16384, *bzi = bz + blk * 128;
        const float *W0i = W0 + blk * 16384, *b0i = b0 + blk * 128;
        const float *W1i = W1 + blk * 16384, *b1i = b1 + blk * 128;

        // -- h += z @ Wz + bz ; r = relu(h) --
        BND();
        pf(s_w, Wzi + 64 * 128, 64 * 512, j);     // Wz hi -> buf0
        u64 bb = pk2(bzi[jj]);
#pragma unroll
        for (int i = 0; i < 16; i++) acc[i] = bb;
        mmW<64>(acc, z2, s_w + WBUF, jj, half);
        BND();
        pf(s_w + WBUF, W0i, 64 * 512, j);         // W0 lo -> buf1
        mmW<64>(acc, z2 + 64 * RSU, s_w, jj, half);
#pragma unroll
        for (int i = 0; i < 16; i++) {            // writes h,r; disjoint from z/w
            float lo, hi; upk2(acc[i], lo, hi);
            float2 h = h2f[i0 + i]; h.x += lo; h.y += hi; h2f[i0 + i] = h;
            r2f[i0 + i] = make_float2(fmaxf(h.x, 0.f), fmaxf(h.y, 0.f));
        }

        // -- net = relu(h) @ W0 + b0 ; r = relu(net) --
        BND();                                     // publishes r
        pf(s_w, W0i + 64 * 128, 64 * 512, j);     // W0 hi -> buf0
        bb = pk2(b0i[jj]);
#pragma unroll
        for (int i = 0; i < 16; i++) acc[i] = bb;
        mmW<64>(acc, r2, s_w + WBUF, jj, half);
        BND();
        pf(s_w + WBUF, W1i, 64 * 512, j);         // W1 lo -> buf1
        mmW<64>(acc, r2 + 64 * RSU, s_w, jj, half);
        __syncthreads();                           // r readers done before overwrite
#pragma unroll
        for (int i = 0; i < 16; i++) {
            float lo, hi; upk2(acc[i], lo, hi);
            r2f[i0 + i] = make_float2(fmaxf(lo, 0.f), fmaxf(hi, 0.f));
        }

        // -- h += relu(net) @ W1 + b1 --
        BND();                                     // publishes r
        pf(s_w, W1i + 64 * 128, 64 * 512, j);     // W1 hi -> buf0
        bb = pk2(b1i[jj]);
#pragma unroll
        for (int i = 0; i < 16; i++) acc[i] = bb;
        mmW<64>(acc, r2, s_w + WBUF, jj, half);
        BND();
        if (blk < 2) pf(s_w + WBUF, Wzi + 16384, 64 * 512, j);  // next blk's Wz lo -> buf1 (FIXED)
        mmW<64>(acc, r2 + 64 * RSU, s_w, jj, half);
        __syncthreads();                           // r readers done before overwrite
#pragma unroll
        for (int i = 0; i < 16; i++) {
            float lo, hi; upk2(acc[i], lo, hi);
            float2 h = h2f[i0 + i]; h.x += lo; h.y += hi; h2f[i0 + i] = h;
            if (blk == 2) r2f[i0 + i] = make_float2(fmaxf(h.x, 0.f), fmaxf(h.y, 0.f));
        }
    }
    __syncthreads();

    // out = relu(h) @ Wout + bout  (Wout tiny: L1-resident LDG)
    if (j < PP * DOUT) {
        int p = j / DOUT, o = j - p * DOUT;
        float a = bout[o];
#pragma unroll 8
        for (int k = 0; k < DHID; k++) a += s_r[k * RSF + p] * Wout[k * DOUT + o];
        (GAUSS ? g_outg : g_outm)[(n0 + p) * DOUT + o] = a;
    }
}

// ---- 4) gaussian params + depth samples + per-ray sort ----
__global__ void gprep_kernel() {
    int r = blockIdx.x * blockDim.x + threadIdx.x;
    if (r >= NRAYS) return;
    float m[NG], sd[NG], d[SMAIN];
#pragma unroll
    for (int g = 0; g < NG; g++) {
        float o0 = g_outg[(r * NG + g) * 2], o1 = g_outg[(r * NG + g) * 2 + 1];
        m[g] = ((float)g + 0.5f) * 25.f + tanhf(o0) * 12.5f;
        sd[g] = 1.f / (1.f + expf(-o1)) * 5.f + 0.001f;
        g_means[r * NG + g] = m[g]; g_stds[r * NG + g] = sd[g];
    }
    for (int i = 0; i < 32; i++) d[i] = 0.5f + (float)i * (99.5f / 31.f);
    int idx = 32;
    for (int g = 0; g < NG; g++)
        for (int jj = 0; jj < 8; jj++)
            d[idx++] = m[g] + (-1.f + (float)jj * (2.f / 7.f)) * 2.f * sd[g];
    for (int i = 0; i < SMAIN; i++) d[i] = fminf(fmaxf(d[i], 0.01f), 100.f);
    for (int i = 1; i < SMAIN; i++) {
        float v = d[i]; int k = i - 1;
        while (k >= 0 && d[k] > v) { d[k + 1] = d[k]; k--; }
        d[k + 1] = v;
    }
    for (int i = 0; i < SMAIN; i++) g_dall[r * SMAIN + i] = d[i];
}

// ---- 5) rendering + losses ----
__device__ __forceinline__ void samp_img(const float *__restrict__ img,
                                         float u, float v, float *o3) {
    float x0f = fminf(fmaxf(floorf(u), 0.f), (float)(IMGW - 2));
    float y0f = fminf(fmaxf(floorf(v), 0.f), (float)(IMGH - 2));
    int x0 = (int)x0f, y0 = (int)y0f;
    float fx = fminf(fmaxf(u - x0f, 0.f), 1.f), fy = fminf(fmaxf(v - y0f, 0.f), 1.f);
    float w00 = (1.f - fx) * (1.f - fy), w10 = fx * (1.f - fy);
    float w01 = (1.f - fx) * fy, w11 = fx * fy;
#pragma unroll
    for (int c = 0; c < 3; c++) {
        int b = c * IMGH * IMGW + y0 * IMGW + x0;
        o3[c] = img[b] * w00 + img[b + 1] * w10 + img[b + IMGW] * w01 + img[b + IMGW + 1] * w11;
    }
}

__global__ void render_kernel(const float *__restrict__ src, const float *__restrict__ tgt,
                              const float *__restrict__ K4, const float *__restrict__ s2t,
                              const float *__restrict__ pix, float *__restrict__ dout) {
    int r = blockIdx.x * blockDim.x + threadIdx.x;
    if (r >= NRAYS) return;
    const float EPSf = 1e-6f;
    float d[SMAIN], w[SMAIN], q[SMAIN];
    for (int s = 0; s < SMAIN; s++) d[s] = g_dall[r * SMAIN + s];
    float T = 1.f, depth = 0.f, c0 = 0.f, c1 = 0.f, c2 = 0.f, wsum = 0.f;
    for (int s = 0; s < SMAIN; s++) {
        float4 o = reinterpret_cast<const float4 *>(g_outm)[r * SMAIN + s];
        float delta = (s < SMAIN - 1) ? (d[s + 1] - d[s]) : 1e10f;
        float alpha = 1.f - expf(-fmaxf(o.x, 0.f) * delta);
        float ww = alpha * T;
        T *= (1.f - alpha + 1e-10f);
        w[s] = ww; wsum += ww; depth += ww * d[s];
        c0 += ww / (1.f + expf(-o.y));
        c1 += ww / (1.f + expf(-o.z));
        c2 += ww / (1.f + expf(-o.w));
    }
    float m[NG], sd[NG], ls[NG];
#pragma unroll
    for (int g = 0; g < NG; g++) {
        m[g] = g_means[r * NG + g]; sd[g] = g_stds[r * NG + g]; ls[g] = logf(sd[g]);
    }
    float qsum = 0.f;
    for (int s = 0; s < SMAIN; s++) {
        float qq = 0.f;
#pragma unroll
        for (int g = 0; g < NG; g++) {
            float t = (d[s] - m[g]) / sd[g];
            qq += expf(-0.5f * t * t - ls[g]);
        }
        q[s] = qq * 0.25f; qsum += q[s];
    }
    float kl = 0.f;
    for (int s = 0; s < SMAIN; s++) {
        float pw = w[s] / (wsum + EPSf), qn = q[s] / (qsum + EPSf);
        kl += pw * (logf(pw + EPSf) - logf(qn + EPSf));
    }
    float d2c = 1e30f;
#pragma unroll
    for (int g = 0; g < NG; g++) d2c = fminf(d2c, fabsf(m[g] - depth));

    float sc[3]; samp_img(src, pix[2 * r], pix[2 * r + 1], sc);
    float closs = fabsf(sc[0] - c0) + fabsf(sc[1] - c1) + fabsf(sc[2] - c2);

    float cx = g_cam[3 * r] * depth, cy = g_cam[3 * r + 1] * depth, cz = g_cam[3 * r + 2] * depth;
    float tx = s2t[0] * cx + s2t[1] * cy + s2t[2]  * cz + s2t[3];
    float ty = s2t[4] * cx + s2t[5] * cy + s2t[6]  * cz + s2t[7];
    float tz = s2t[8] * cx + s2t[9] * cy + s2t[10] * cz + s2t[11];
    float pxp = K4[0] * tx + K4[1] * ty + K4[2] * tz;
    float pyp = K4[3] * tx + K4[4] * ty + K4[5] * tz;
    float pzp = K4[6] * tx + K4[7] * ty + K4[8] * tz;
    float tc[3]; samp_img(tgt, pxp / (pzp + EPSf), pyp / (pzp + EPSf), tc);
    float mask = (depth < 30.f) ? 1.f : 0.f;
    g_kl[r] = kl; g_d2c[r] = d2c; g_colL[r] = closs;
    g_rn[r] = mask * (fabsf(tc[0] - sc[0]) + fabsf(tc[1] - sc[1]) + fabsf(tc[2] - sc[2])) * (1.f / 3.f);
    g_rd[r] = mask;
    dout[1 + r] = depth;
    dout[1 + NRAYS + 3 * r + 0] = c0;
    dout[1 + NRAYS + 3 * r + 1] = c1;
    dout[1 + NRAYS + 3 * r + 2] = c2;
}

// ---- 6) deterministic scalar reduction ----
__global__ void reduce_kernel(float *__restrict__ dout) {
    __shared__ float sm[5][256];
    int t = threadIdx.x;
    float a[5] = {0, 0, 0, 0, 0};
    for (int r = t; r < NRAYS; r += 256) {
        a[0] += g_kl[r]; a[1] += g_d2c[r]; a[2] += g_colL[r]; a[3] += g_rn[r]; a[4] += g_rd[r];
    }
    for (int c = 0; c < 5; c++) sm[c][t] = a[c];
    __syncthreads();
    for (int s = 128; s > 0; s >>= 1) {
        if (t < s) for (int c = 0; c < 5; c++) sm[c][t] += sm[c][t + s];
        __syncthreads();
    }
    if (t == 0)
        dout[0] = sm[0][0] * (1.f / NRAYS) + 0.01f * sm[1][0] * (1.f / NRAYS) +
                  sm[2][0] * (1.f / (3.f * NRAYS)) + sm[3][0] / (sm[4][0] + 1e-6f);
}

extern "C" void kernel_launch(void* const* d_in, const int* in_sizes, int n_in,
                              void* d_out, int out_size) {
    const float *bev = (const float *)d_in[0];
    const float *src = (const float *)d_in[1];
    const float *tgt = (const float *)d_in[2];
    const float *K4  = (const float *)d_in[3];
    const float *s2i = (const float *)d_in[4];
    const float *s2t = (const float *)d_in[5];
    const float *pix = (const float *)d_in[6];
    const float *const *m1 = (const float *const *)&d_in[7];   // main MLP (4 out)
    const float *const *m2 = (const float *const *)&d_in[17];  // gauss MLP (2 out)
    float *dout = (float *)d_out;

    int smem = (3 * 128 * RSF + 2 * WBUF) * 4;   // 169984 B
    cudaFuncSetAttribute(decode_kernel<true>,  cudaFuncAttributeMaxDynamicSharedMemorySize, smem);
    cudaFuncSetAttribute(decode_kernel<false>, cudaFuncAttributeMaxDynamicSharedMemorySize, smem);

    transpose_kernel<<<dim3(7, 4, 1600), dim3(32, 8)>>>(bev);
    setup_kernel<<<32, 128>>>(K4, s2i, pix);
    decode_kernel<true><<<NRAYS * NG / PP, 256, smem>>>(
        s2i, m2[0], m2[1], m2[2], m2[3], m2[4], m2[5], m2[6], m2[7], m2[8], m2[9]);
    gprep_kernel<<<64, 64>>>();
    decode_kernel<false><<<NRAYS * SMAIN / PP, 256, smem>>>(
        s2i, m1[0], m1[1], m1[2], m1[3], m1[4], m1[5], m1[6], m1[7], m1[8], m1[9]);
    render_kernel<<<64, 64>>>(src, tgt, K4, s2t, pix, dout);
    reduce_kernel<<<1, 256>>>(dout);
}

// round 14
// speedup vs baseline: 3.5527x; 3.2773x over previous
#include <cuda_runtime.h>
#include <cuda_bf16.h>
typedef unsigned long long u64;
#define NRAYS 4096
#define SMAIN 64
#define NG 4
#define IMGH 900
#define IMGW 1600

// tile geometry
#define AS 272            // A/Z row stride bytes (128 bf16 + pad, 16B aligned)
#define ALO 34816         // lo offset within A/Z tile (128*272)
#define WS 144            // W half-row stride bytes (64 bf16 + pad)
#define WLO 18432         // lo offset within W half (128*144)
#define WCHUNK 36864      // one half-layer image (hi+lo)
#define NCHUNK 19         // 1 input + 9 layers * 2 halves
#define DYNSM (2*WCHUNK + 2*(2*ALO))   // 212992

__device__ __align__(16) float g_vox[8*200*200*128];
__device__ float g_dirs[NRAYS*3], g_view[NRAYS*3], g_cam[NRAYS*3];
__device__ float g_outg[NRAYS*NG*2], g_means[NRAYS*NG], g_stds[NRAYS*NG];
__device__ float g_dall[NRAYS*SMAIN];
__device__ __align__(16) float g_outm[NRAYS*SMAIN*4];
__device__ float g_kl[NRAYS], g_d2c[NRAYS], g_colL[NRAYS], g_rn[NRAYS], g_rd[NRAYS];
__device__ __align__(16) char g_wimg[2][NCHUNK*WCHUNK];

__device__ __forceinline__ unsigned smem_u32(const void *p) {
    unsigned a; asm("{ .reg .u64 t; cvta.to.shared.u64 t, %1; cvt.u32.u64 %0, t; }":"=r"(a):"l"(p)); return a;
}
__device__ __forceinline__ void ldm4(unsigned *r, unsigned a) {
    asm volatile("ldmatrix.sync.aligned.m8n8.x4.shared.b16 {%0,%1,%2,%3},[%4];"
        :"=r"(r[0]),"=r"(r[1]),"=r"(r[2]),"=r"(r[3]):"r"(a));
}
__device__ __forceinline__ void ldm2(unsigned *r, unsigned a) {
    asm volatile("ldmatrix.sync.aligned.m8n8.x2.shared.b16 {%0,%1},[%2];"
        :"=r"(r[0]),"=r"(r[1]):"r"(a));
}
__device__ __forceinline__ void mma16816(float *d, const unsigned *a, const unsigned *b) {
    asm volatile("mma.sync.aligned.m16n8k16.row.col.f32.bf16.bf16.f32 "
        "{%0,%1,%2,%3},{%4,%5,%6,%7},{%8,%9},{%0,%1,%2,%3};"
        :"+f"(d[0]),"+f"(d[1]),"+f"(d[2]),"+f"(d[3])
        :"r"(a[0]),"r"(a[1]),"r"(a[2]),"r"(a[3]),"r"(b[0]),"r"(b[1]));
}
__device__ __forceinline__ void pf(const void *sdst, const char *g, int bytes, int j) {
    unsigned sa = smem_u32(sdst);
    for (int off = j*16; off < bytes; off += 256*16)
        asm volatile("cp.async.cg.shared.global [%0], [%1], 16;" :: "r"(sa+off), "l"(g+off));
    asm volatile("cp.async.commit_group;" ::: "memory");
}
#define BND() { asm volatile("cp.async.wait_group 0;" ::: "memory"); __syncthreads(); }

// 4 k16-steps of the 3-pass split MMA. src/wb are smem addrs (hi; lo at fixed offsets).
__device__ __forceinline__ void mma_half(float acc[2][8][4], unsigned src, unsigned wb,
                                         int kbase, int lane, int wm, int wn) {
#pragma unroll
    for (int ks = 0; ks < 4; ks++) {
        int kg = kbase + ks*16;
        unsigned ah[2][4], al[2][4];
#pragma unroll
        for (int mt = 0; mt < 2; mt++) {
            unsigned ra = src + (wm*32 + mt*16 + (lane & 15))*AS + ((lane >> 4)*8 + kg)*2;
            ldm4(ah[mt], ra); ldm4(al[mt], ra + ALO);
        }
#pragma unroll
        for (int nt = 0; nt < 8; nt++) {
            unsigned rb = wb + (wn*64 + nt*8 + (lane & 7))*WS + (((lane >> 3) & 1)*8 + ks*16)*2;
            unsigned bh[2], bl[2];
            ldm2(bh, rb); ldm2(bl, rb + WLO);
#pragma unroll
            for (int mt = 0; mt < 2; mt++) {
                mma16816(acc[mt][nt], ah[mt], bh);
                mma16816(acc[mt][nt], ah[mt], bl);
                mma16816(acc[mt][nt], al[mt], bh);
            }
        }
    }
}

__global__ void transpose_kernel(const float *__restrict__ bev) {
    __shared__ float tile[32][33];
    int dh = blockIdx.z, d = dh/200, h = dh - d*200;
    int w0 = blockIdx.x*32, c0 = blockIdx.y*32, tx = threadIdx.x, ty = threadIdx.y;
#pragma unroll
    for (int i = 0; i < 32; i += 8) {
        int c = c0+ty+i, w = w0+tx;
        if (w < 200) tile[ty+i][tx] = bev[(c*8+d)*40000 + h*200 + w];
    }
    __syncthreads();
#pragma unroll
    for (int i = 0; i < 32; i += 8) {
        int w = w0+ty+i, c = c0+tx;
        if (w < 200) g_vox[((d*200+h)*200+w)*128 + c] = tile[tx][ty+i];
    }
}

// weight images: W^T rows n, cols k, bf16 hi/lo, padded rows, chunked per half-layer
__global__ void wprep_kernel(const float *__restrict__ Win0, const float *__restrict__ Wz0,
                             const float *__restrict__ W00,  const float *__restrict__ W10,
                             const float *__restrict__ Win1, const float *__restrict__ Wz1,
                             const float *__restrict__ W01,  const float *__restrict__ W11) {
    int idx = blockIdx.x*blockDim.x + threadIdx.x, mlp = blockIdx.y;
    const float *Win = mlp ? Win1 : Win0, *Wz = mlp ? Wz1 : Wz0;
    const float *W0p = mlp ? W01 : W00, *W1p = mlp ? W11 : W10;
    char *out = g_wimg[mlp];
    float v; unsigned off;
    if (idx < 8192) {                       // input chunk: n=128, k=64 (k>=42 zero)
        int n = idx >> 6, k = idx & 63;
        v = (k < 42) ? Win[k*128 + n] : 0.f;
        off = n*WS + k*2;
    } else {
        int e = idx - 8192; if (e >= 9*16384) return;
        int mat = e >> 14, r = e & 16383, n = r >> 7, k = r & 127;
        int blk = mat/3, t = mat%3;
        const float *W = (t==0 ? Wz : t==1 ? W0p : W1p) + blk*16384;
        v = W[k*128 + n];
        unsigned chunk = 1u + (unsigned)mat*2u + (k >= 64 ? 1u : 0u);
        off = chunk*WCHUNK + n*WS + (k & 63)*2;
    }
    __nv_bfloat16 hi = __float2bfloat16(v);
    __nv_bfloat16 lo = __float2bfloat16(v - __bfloat162float(hi));
    *(__nv_bfloat16 *)(out + off) = hi;
    *(__nv_bfloat16 *)(out + WLO + off) = lo;
}

__global__ void setup_kernel(const float *__restrict__ K4, const float *__restrict__ s2i,
                             const float *__restrict__ pix) {
    int r = blockIdx.x*blockDim.x + threadIdx.x;
    if (r >= NRAYS) return;
    float a = K4[0], b = K4[1], c = K4[2], d = K4[3], e = K4[4], f = K4[5];
    float g = K4[6], h = K4[7], i9 = K4[8];
    float A = e*i9-f*h, B = c*h-b*i9, C = b*f-c*e, D = f*g-d*i9, E = a*i9-c*g, F = c*d-a*f;
    float G = d*h-e*g, H = b*g-a*h, I = a*e-b*d;
    float idet = 1.f/(a*A + b*D + c*G);
    float u = pix[2*r], v = pix[2*r+1];
    float cx = (A*u+B*v+C)*idet, cy = (D*u+E*v+F)*idet, cz = (G*u+H*v+I)*idet;
    g_cam[3*r] = cx; g_cam[3*r+1] = cy; g_cam[3*r+2] = cz;
    float dx = s2i[0]*cx+s2i[1]*cy+s2i[2]*cz, dy = s2i[4]*cx+s2i[5]*cy+s2i[6]*cz,
          dz = s2i[8]*cx+s2i[9]*cy+s2i[10]*cz;
    g_dirs[3*r] = dx; g_dirs[3*r+1] = dy; g_dirs[3*r+2] = dz;
    float inv = rsqrtf(dx*dx+dy*dy+dz*dz);
    g_view[3*r] = dx*inv; g_view[3*r+1] = dy*inv; g_view[3*r+2] = dz*inv;
}

__device__ __forceinline__ void storeA(char *sA, int row, int col, float v0, float v1) {
    __nv_bfloat162 hh = __floats2bfloat162_rn(v0, v1);
    __nv_bfloat162 ll = __floats2bfloat162_rn(v0 - __bfloat162float(hh.x), v1 - __bfloat162float(hh.y));
    unsigned off = row*AS + col*2;
    *(unsigned *)(sA + off) = *(unsigned *)&hh;
    *(unsigned *)(sA + ALO + off) = *(unsigned *)&ll;
}

template <bool GAUSS>
__global__ void __launch_bounds__(256, 1) decode_mma(
        const float *__restrict__ s2i,
        const float *__restrict__ bin, const float *__restrict__ bz,
        const float *__restrict__ b0,  const float *__restrict__ b1,
        const float *__restrict__ Wout,const float *__restrict__ bout) {
    constexpr int S = GAUSS ? NG : SMAIN;
    constexpr int DOUT = GAUSS ? 2 : 4;
    extern __shared__ char dynsm[];
    __shared__ float s_bias[10][128], s_wout[128*4], s_partial[2][128][4], s_f[128][3];
    __shared__ int s_base[128], s_val[128];

    const int tid = threadIdx.x, lane = tid & 31, w = tid >> 5;
    const int q = lane >> 2, tq = lane & 3, wm = w & 3, wn = w >> 2;
    const int n0 = blockIdx.x*128;
    const char *wimg = g_wimg[GAUSS ? 1 : 0];
    char *sW = dynsm, *sA = sW + 2*WCHUNK, *sZ = sA + 2*ALO;
    const unsigned uW = smem_u32(sW), uA = smem_u32(sA), uZ = smem_u32(sZ);

    pf(sW, wimg, WCHUNK, tid);                         // chunk0 (input layer)

    if (tid < 128) {
        s_bias[0][tid] = bin[tid];
#pragma unroll
        for (int blk = 0; blk < 3; blk++) {
            s_bias[1+blk*3+0][tid] = bz[blk*128+tid];
            s_bias[1+blk*3+1][tid] = b0[blk*128+tid];
            s_bias[1+blk*3+2][tid] = b1[blk*128+tid];
        }
    }
    for (int i = tid; i < 128*DOUT; i += 256) s_wout[i] = Wout[i];

    // geometry + features + Z gather
    if (tid < 128) {
        int p = tid, n = n0+p, r = n/S, s = n - r*S;
        float dpt = GAUSS ? ((float)s + 0.5f)*25.0f : g_dall[n];
        float ptx = s2i[3]  + g_dirs[3*r]*dpt;
        float pty = s2i[7]  + g_dirs[3*r+1]*dpt;
        float ptz = s2i[11] + g_dirs[3*r+2]*dpt;
        float gx = (ptx+51.2f)*(199.0f/102.4f), gy = (pty+51.2f)*(199.0f/102.4f), gz = (ptz+5.0f)*(7.0f/8.0f);
        s_val[p] = (gx>=0.f)&(gx<=199.f)&(gy>=0.f)&(gy<=199.f)&(gz>=0.f)&(gz<=7.f);
        int x0 = min(max((int)floorf(gx),0),198), y0 = min(max((int)floorf(gy),0),198), z0 = min(max((int)floorf(gz),0),6);
        s_f[p][0] = fminf(fmaxf(gx-(float)x0,0.f),1.f);
        s_f[p][1] = fminf(fmaxf(gy-(float)y0,0.f),1.f);
        s_f[p][2] = fminf(fmaxf(gz-(float)z0,0.f),1.f);
        s_base[p] = ((z0*200+x0)*200+y0)*128;
        float f[64];
#pragma unroll
        for (int k = 0; k < 64; k++) f[k] = 0.f;
        f[0] = ptx; f[1] = pty; f[2] = ptz;
        float xyz[3] = {ptx, pty, ptz};
#pragma unroll
        for (int fr = 0; fr < 6; fr++) {
            float sc = 3.14159265358979323846f*(float)(1 << fr);
#pragma unroll
            for (int t = 0; t < 3; t++) {
                float xx = xyz[t]*sc;
                f[3+fr*6+t] = sinf(xx); f[3+fr*6+3+t] = cosf(xx);
            }
        }
        f[39] = g_view[3*r]; f[40] = g_view[3*r+1]; f[41] = g_view[3*r+2];
#pragma unroll
        for (int i = 0; i < 32; i++) storeA(sA, p, 2*i, f[2*i], f[2*i+1]);
    }
    __syncthreads();     // s_val/s_f/s_base visible for gather
    {
        int c = tid & 127, p0 = (tid >> 7)*64;
        for (int p = p0; p < p0+64; p++) {
            float zv = 0.f;
            if (s_val[p]) {
                const float *vp = g_vox + s_base[p] + c;
                float fx = s_f[p][0], fy = s_f[p][1], fz = s_f[p][2];
                float ox = 1.f-fx, oy = 1.f-fy, oz = 1.f-fz;
                float c00 = vp[0]*ox + vp[25600]*fx, c01 = vp[128]*ox + vp[25728]*fx;
                float c10 = vp[5120000]*ox + vp[5145600]*fx, c11 = vp[5120128]*ox + vp[5145728]*fx;
                zv = (c00*oy + c01*fy)*oz + (c10*oy + c11*fy)*fz;
            }
            __nv_bfloat16 zh = __float2bfloat16(zv);
            __nv_bfloat16 zl = __float2bfloat16(zv - __bfloat162float(zh));
            unsigned off = p*AS + c*2;
            *(__nv_bfloat16 *)(sZ + off) = zh;
            *(__nv_bfloat16 *)(sZ + ALO + off) = zl;
        }
    }

    float h[2][8][4], acc[2][8][4];
    int cur = 0;

    // input layer: h = x @ Win + bin   (K=64, chunk0 in buf0)
    BND();
    pf(sW + WCHUNK, wimg + WCHUNK, WCHUNK, tid);       // chunk1 -> buf1
#pragma unroll
    for (int mt = 0; mt < 2; mt++)
#pragma unroll
        for (int nt = 0; nt < 8; nt++)
#pragma unroll
            for (int c = 0; c < 4; c++) acc[mt][nt][c] = 0.f;
    mma_half(acc, uA, uW, 0, lane, wm, wn);
    cur = 1;
#pragma unroll
    for (int mt = 0; mt < 2; mt++)
#pragma unroll
        for (int nt = 0; nt < 8; nt++)
#pragma unroll
            for (int c = 0; c < 4; c++)
                h[mt][nt][c] = acc[mt][nt][c] + s_bias[0][wn*64 + nt*8 + tq*2 + (c & 1)];

    for (int st = 0; st < 9; st++) {
        int t = st % 3;
        unsigned src = (t == 0) ? uZ : uA;
#pragma unroll
        for (int mt = 0; mt < 2; mt++)
#pragma unroll
            for (int nt = 0; nt < 8; nt++)
#pragma unroll
                for (int c = 0; c < 4; c++) acc[mt][nt][c] = 0.f;
        // half 0
        BND();
        if (cur + 1 < NCHUNK) pf(sW + ((cur+1)&1)*WCHUNK, wimg + (cur+1)*WCHUNK, WCHUNK, tid);
        mma_half(acc, src, uW + (cur&1)*WCHUNK, 0, lane, wm, wn);
        cur++;
        // half 1
        BND();
        if (cur + 1 < NCHUNK) pf(sW + ((cur+1)&1)*WCHUNK, wimg + (cur+1)*WCHUNK, WCHUNK, tid);
        mma_half(acc, src, uW + (cur&1)*WCHUNK, 64, lane, wm, wn);
        cur++;
        __syncthreads();          // all warps done reading A/Z/W before A overwrite
        int bi = 1 + (st/3)*3 + t;
#pragma unroll
        for (int mt = 0; mt < 2; mt++)
#pragma unroll
            for (int nt = 0; nt < 8; nt++) {
                int colb = wn*64 + nt*8 + tq*2;
                float bb0 = s_bias[bi][colb], bb1 = s_bias[bi][colb+1];
                if (t == 1) {     // net = D + b0 ; A = split(relu(net)) ; h unchanged
                    float n0v = acc[mt][nt][0] + bb0, n1v = acc[mt][nt][1] + bb1;
                    float n2v = acc[mt][nt][2] + bb0, n3v = acc[mt][nt][3] + bb1;
                    storeA(sA, wm*32 + mt*16 + q,     colb, fmaxf(n0v,0.f), fmaxf(n1v,0.f));
                    storeA(sA, wm*32 + mt*16 + q + 8, colb, fmaxf(n2v,0.f), fmaxf(n3v,0.f));
                } else {          // h += D + b ; if t==0: A = split(relu(h))
                    h[mt][nt][0] += acc[mt][nt][0] + bb0;
                    h[mt][nt][1] += acc[mt][nt][1] + bb1;
                    h[mt][nt][2] += acc[mt][nt][2] + bb0;
                    h[mt][nt][3] += acc[mt][nt][3] + bb1;
                    if (t == 0) {
                        storeA(sA, wm*32 + mt*16 + q,     colb, fmaxf(h[mt][nt][0],0.f), fmaxf(h[mt][nt][1],0.f));
                        storeA(sA, wm*32 + mt*16 + q + 8, colb, fmaxf(h[mt][nt][2],0.f), fmaxf(h[mt][nt][3],0.f));
                    }
                }
            }
        __syncthreads();
    }

    // final: out = relu(h) @ Wout (+bout later), quad + cross-warp-column reduce
#pragma unroll
    for (int mt = 0; mt < 2; mt++)
#pragma unroll
        for (int half = 0; half < 2; half++) {
            int row = wm*32 + mt*16 + q + half*8;
            float po[4] = {0,0,0,0};
#pragma unroll
            for (int nt = 0; nt < 8; nt++) {
                int colb = wn*64 + nt*8 + tq*2;
                float r0v = fmaxf(h[mt][nt][half*2+0], 0.f);
                float r1v = fmaxf(h[mt][nt][half*2+1], 0.f);
#pragma unroll
                for (int o = 0; o < DOUT; o++)
                    po[o] += r0v*s_wout[colb*DOUT+o] + r1v*s_wout[(colb+1)*DOUT+o];
            }
#pragma unroll
            for (int o = 0; o < DOUT; o++) {
                po[o] += __shfl_xor_sync(0xffffffffu, po[o], 1);
                po[o] += __shfl_xor_sync(0xffffffffu, po[o], 2);
            }
            if (tq == 0)
#pragma unroll
                for (int o = 0; o < DOUT; o++) s_partial[wn][row][o] = po[o];
        }
    __syncthreads();
    if (tid < 128)
#pragma unroll
        for (int o = 0; o < DOUT; o++)
            (GAUSS ? g_outg : g_outm)[(n0+tid)*DOUT+o] =
                s_partial[0][tid][o] + s_partial[1][tid][o] + bout[o];
}

__global__ void gprep_kernel() {
    int r = blockIdx.x*blockDim.x + threadIdx.x;
    if (r >= NRAYS) return;
    float m[NG], sd[NG], d[SMAIN];
#pragma unroll
    for (int g = 0; g < NG; g++) {
        float o0 = g_outg[(r*NG+g)*2], o1 = g_outg[(r*NG+g)*2+1];
        m[g] = ((float)g+0.5f)*25.f + tanhf(o0)*12.5f;
        sd[g] = 1.f/(1.f+expf(-o1))*5.f + 0.001f;
        g_means[r*NG+g] = m[g]; g_stds[r*NG+g] = sd[g];
    }
    for (int i = 0; i < 32; i++) d[i] = 0.5f + (float)i*(99.5f/31.f);
    int idx = 32;
    for (int g = 0; g < NG; g++)
        for (int jj = 0; jj < 8; jj++)
            d[idx++] = m[g] + (-1.f + (float)jj*(2.f/7.f))*2.f*sd[g];
    for (int i = 0; i < SMAIN; i++) d[i] = fminf(fmaxf(d[i], 0.01f), 100.f);
    for (int i = 1; i < SMAIN; i++) {
        float v = d[i]; int k = i-1;
        while (k >= 0 && d[k] > v) { d[k+1] = d[k]; k--; }
        d[k+1] = v;
    }
    for (int i = 0; i < SMAIN; i++) g_dall[r*SMAIN+i] = d[i];
}

__device__ __forceinline__ void samp_img(const float *__restrict__ img, float u, float v, float *o3) {
    float x0f = fminf(fmaxf(floorf(u), 0.f), (float)(IMGW-2));
    float y0f = fminf(fmaxf(floorf(v), 0.f), (float)(IMGH-2));
    int x0 = (int)x0f, y0 = (int)y0f;
    float fx = fminf(fmaxf(u-x0f,0.f),1.f), fy = fminf(fmaxf(v-y0f,0.f),1.f);
    float w00 = (1.f-fx)*(1.f-fy), w10 = fx*(1.f-fy), w01 = (1.f-fx)*fy, w11 = fx*fy;
#pragma unroll
    for (int c = 0; c < 3; c++) {
        int b = c*IMGH*IMGW + y0*IMGW + x0;
        o3[c] = img[b]*w00 + img[b+1]*w10 + img[b+IMGW]*w01 + img[b+IMGW+1]*w11;
    }
}

__global__ void render_kernel(const float *__restrict__ src, const float *__restrict__ tgt,
                              const float *__restrict__ K4, const float *__restrict__ s2t,
                              const float *__restrict__ pix, float *__restrict__ dout) {
    int r = blockIdx.x*blockDim.x + threadIdx.x;
    if (r >= NRAYS) return;
    const float EPSf = 1e-6f;
    float d[SMAIN], w[SMAIN], q[SMAIN];
    for (int s = 0; s < SMAIN; s++) d[s] = g_dall[r*SMAIN+s];
    float T = 1.f, depth = 0.f, c0 = 0.f, c1 = 0.f, c2 = 0.f, wsum = 0.f;
    for (int s = 0; s < SMAIN; s++) {
        float4 o = reinterpret_cast<const float4 *>(g_outm)[r*SMAIN+s];
        float delta = (s < SMAIN-1) ? (d[s+1]-d[s]) : 1e10f;
        float alpha = 1.f - expf(-fmaxf(o.x, 0.f)*delta);
        float ww = alpha*T; T *= (1.f - alpha + 1e-10f);
        w[s] = ww; wsum += ww; depth += ww*d[s];
        c0 += ww/(1.f+expf(-o.y)); c1 += ww/(1.f+expf(-o.z)); c2 += ww/(1.f+expf(-o.w));
    }
    float m[NG], sd[NG], ls[NG];
#pragma unroll
    for (int g = 0; g < NG; g++) { m[g] = g_means[r*NG+g]; sd[g] = g_stds[r*NG+g]; ls[g] = logf(sd[g]); }
    float qsum = 0.f;
    for (int s = 0; s < SMAIN; s++) {
        float qq = 0.f;
#pragma unroll
        for (int g = 0; g < NG; g++) {
            float t = (d[s]-m[g])/sd[g];
            qq += expf(-0.5f*t*t - ls[g]);
        }
        q[s] = qq*0.25f; qsum += q[s];
    }
    float kl = 0.f;
    for (int s = 0; s < SMAIN; s++) {
        float pw = w[s]/(wsum+EPSf), qn = q[s]/(qsum+EPSf);
        kl += pw*(logf(pw+EPSf) - logf(qn+EPSf));
    }
    float d2c = 1e30f;
#pragma unroll
    for (int g = 0; g < NG; g++) d2c = fminf(d2c, fabsf(m[g]-depth));
    float sc[3]; samp_img(src, pix[2*r], pix[2*r+1], sc);
    float closs = fabsf(sc[0]-c0) + fabsf(sc[1]-c1) + fabsf(sc[2]-c2);
    float cx = g_cam[3*r]*depth, cy = g_cam[3*r+1]*depth, cz = g_cam[3*r+2]*depth;
    float tx = s2t[0]*cx+s2t[1]*cy+s2t[2]*cz+s2t[3];
    float ty = s2t[4]*cx+s2t[5]*cy+s2t[6]*cz+s2t[7];
    float tz = s2t[8]*cx+s2t[9]*cy+s2t[10]*cz+s2t[11];
    float pxp = K4[0]*tx+K4[1]*ty+K4[2]*tz, pyp = K4[3]*tx+K4[4]*ty+K4[5]*tz, pzp = K4[6]*tx+K4[7]*ty+K4[8]*tz;
    float tc[3]; samp_img(tgt, pxp/(pzp+EPSf), pyp/(pzp+EPSf), tc);
    float mask = (depth < 30.f) ? 1.f : 0.f;
    g_kl[r] = kl; g_d2c[r] = d2c; g_colL[r] = closs;
    g_rn[r] = mask*(fabsf(tc[0]-sc[0]) + fabsf(tc[1]-sc[1]) + fabsf(tc[2]-sc[2]))*(1.f/3.f);
    g_rd[r] = mask;
    dout[1+r] = depth;
    dout[1+NRAYS+3*r+0] = c0; dout[1+NRAYS+3*r+1] = c1; dout[1+NRAYS+3*r+2] = c2;
}

__global__ void reduce_kernel(float *__restrict__ dout) {
    __shared__ float sm[5][256];
    int t = threadIdx.x;
    float a[5] = {0,0,0,0,0};
    for (int r = t; r < NRAYS; r += 256) {
        a[0] += g_kl[r]; a[1] += g_d2c[r]; a[2] += g_colL[r]; a[3] += g_rn[r]; a[4] += g_rd[r];
    }
    for (int c = 0; c < 5; c++) sm[c][t] = a[c];
    __syncthreads();
    for (int s = 128; s > 0; s >>= 1) {
        if (t < s) for (int c = 0; c < 5; c++) sm[c][t] += sm[c][t+s];
        __syncthreads();
    }
    if (t == 0)
        dout[0] = sm[0][0]*(1.f/NRAYS) + 0.01f*sm[1][0]*(1.f/NRAYS) +
                  sm[2][0]*(1.f/(3.f*NRAYS)) + sm[3][0]/(sm[4][0]+1e-6f);
}

extern "C" void kernel_launch(void* const* d_in, const int* in_sizes, int n_in,
                              void* d_out, int out_size) {
    const float *bev = (const float *)d_in[0];
    const float *src = (const float *)d_in[1];
    const float *tgt = (const float *)d_in[2];
    const float *K4  = (const float *)d_in[3];
    const float *s2i = (const float *)d_in[4];
    const float *s2t = (const float *)d_in[5];
    const float *pix = (const float *)d_in[6];
    const float *const *m1 = (const float *const *)&d_in[7];
    const float *const *m2 = (const float *const *)&d_in[17];
    float *dout = (float *)d_out;

    cudaFuncSetAttribute(decode_mma<true>,  cudaFuncAttributeMaxDynamicSharedMemorySize, DYNSM);
    cudaFuncSetAttribute(decode_mma<false>, cudaFuncAttributeMaxDynamicSharedMemorySize, DYNSM);

    transpose_kernel<<<dim3(7,4,1600), dim3(32,8)>>>(bev);
    wprep_kernel<<<dim3(608,2), 256>>>(m1[0], m1[2], m1[4], m1[6], m2[0], m2[2], m2[4], m2[6]);
    setup_kernel<<<32, 128>>>(K4, s2i, pix);
    decode_mma<true><<<NRAYS*NG/128, 256, DYNSM>>>(s2i, m2[1], m2[3], m2[5], m2[7], m2[8], m2[9]);
    gprep_kernel<<<64, 64>>>();
    decode_mma<false><<<NRAYS*SMAIN/128, 256, DYNSM>>>(s2i, m1[1], m1[3], m1[5], m1[7], m1[8], m1[9]);
    render_kernel<<<64, 64>>>(src, tgt, K4, s2t, pix, dout);
    reduce_kernel<<<1, 256>>>(dout);
}

// round 15
// speedup vs baseline: 3.6695x; 1.0329x over previous
#include <cuda_runtime.h>
#include <cuda_bf16.h>
typedef unsigned long long u64;
#define NRAYS 4096
#define SMAIN 64
#define NG 4
#define IMGH 900
#define IMGW 1600

// tile geometry
#define AS 272            // A/Z row stride bytes (128 bf16 + pad, 16B aligned)
#define ALO 34816         // lo offset within A/Z tile (128*272)
#define WS 144            // W half-row stride bytes (64 bf16 + pad)
#define WLO 18432         // lo offset within W half (128*144)
#define WCHUNK 36864      // one half-layer image (hi+lo)
#define NCHUNK 19         // 1 input + 9 layers * 2 halves
#define DYNSM (2*WCHUNK + 2*(2*ALO))   // 212992
#define NT 512            // decode threads

__device__ __align__(16) float g_vox[8*200*200*128];
__device__ float g_dirs[NRAYS*3], g_view[NRAYS*3], g_cam[NRAYS*3];
__device__ float g_outg[NRAYS*NG*2], g_means[NRAYS*NG], g_stds[NRAYS*NG];
__device__ float g_dall[NRAYS*SMAIN];
__device__ __align__(16) float g_outm[NRAYS*SMAIN*4];
__device__ float g_kl[NRAYS], g_d2c[NRAYS], g_colL[NRAYS], g_rn[NRAYS], g_rd[NRAYS];
__device__ __align__(16) char g_wimg[2][NCHUNK*WCHUNK];

__device__ __forceinline__ unsigned smem_u32(const void *p) {
    unsigned a; asm("{ .reg .u64 t; cvta.to.shared.u64 t, %1; cvt.u32.u64 %0, t; }":"=r"(a):"l"(p)); return a;
}
__device__ __forceinline__ void ldm4(unsigned *r, unsigned a) {
    asm volatile("ldmatrix.sync.aligned.m8n8.x4.shared.b16 {%0,%1,%2,%3},[%4];"
        :"=r"(r[0]),"=r"(r[1]),"=r"(r[2]),"=r"(r[3]):"r"(a));
}
__device__ __forceinline__ void mma16816(float *d, const unsigned *a, const unsigned *b) {
    asm volatile("mma.sync.aligned.m16n8k16.row.col.f32.bf16.bf16.f32 "
        "{%0,%1,%2,%3},{%4,%5,%6,%7},{%8,%9},{%0,%1,%2,%3};"
        :"+f"(d[0]),"+f"(d[1]),"+f"(d[2]),"+f"(d[3])
        :"r"(a[0]),"r"(a[1]),"r"(a[2]),"r"(a[3]),"r"(b[0]),"r"(b[1]));
}
__device__ __forceinline__ void pf(const void *sdst, const char *g, int bytes, int j) {
    unsigned sa = smem_u32(sdst);
    for (int off = j*16; off < bytes; off += NT*16)
        asm volatile("cp.async.cg.shared.global [%0], [%1], 16;" :: "r"(sa+off), "l"(g+off));
    asm volatile("cp.async.commit_group;" ::: "memory");
}
#define BND() { asm volatile("cp.async.wait_group 0;" ::: "memory"); __syncthreads(); }

// 4 k16-steps of the 3-pass split MMA for one 32x32 warp tile.
// B loaded with x4 ldmatrix covering two n8 tiles per instruction.
__device__ __forceinline__ void mma_half(float acc[2][4][4], unsigned src, unsigned wb,
                                         int kbase, int lane, int wm, int wn) {
#pragma unroll
    for (int ks = 0; ks < 4; ks++) {
        int kg = kbase + ks*16;
        unsigned ah[2][4], al[2][4];
#pragma unroll
        for (int mt = 0; mt < 2; mt++) {
            unsigned ra = src + (wm*32 + mt*16 + (lane & 15))*AS + ((lane >> 4)*8 + kg)*2;
            ldm4(ah[mt], ra); ldm4(al[mt], ra + ALO);
        }
#pragma unroll
        for (int ntp = 0; ntp < 2; ntp++) {
            // m0,m1 = nt (k+0,k+8); m2,m3 = nt+1 (k+0,k+8)
            unsigned rb = wb + (wn*32 + ntp*16 + (lane>>4)*8 + (lane&7))*WS
                             + (((lane>>3)&1)*8 + ks*16)*2;
            unsigned bh[4], bl[4];
            ldm4(bh, rb); ldm4(bl, rb + WLO);
#pragma unroll
            for (int sub = 0; sub < 2; sub++) {
                int nt = ntp*2 + sub;
#pragma unroll
                for (int mt = 0; mt < 2; mt++) {
                    mma16816(acc[mt][nt], ah[mt], bh + sub*2);
                    mma16816(acc[mt][nt], ah[mt], bl + sub*2);
                    mma16816(acc[mt][nt], al[mt], bh + sub*2);
                }
            }
        }
    }
}

__global__ void transpose_kernel(const float *__restrict__ bev) {
    __shared__ float tile[32][33];
    int dh = blockIdx.z, d = dh/200, h = dh - d*200;
    int w0 = blockIdx.x*32, c0 = blockIdx.y*32, tx = threadIdx.x, ty = threadIdx.y;
#pragma unroll
    for (int i = 0; i < 32; i += 8) {
        int c = c0+ty+i, w = w0+tx;
        if (w < 200) tile[ty+i][tx] = bev[(c*8+d)*40000 + h*200 + w];
    }
    __syncthreads();
#pragma unroll
    for (int i = 0; i < 32; i += 8) {
        int w = w0+ty+i, c = c0+tx;
        if (w < 200) g_vox[((d*200+h)*200+w)*128 + c] = tile[tx][ty+i];
    }
}

__global__ void wprep_kernel(const float *__restrict__ Win0, const float *__restrict__ Wz0,
                             const float *__restrict__ W00,  const float *__restrict__ W10,
                             const float *__restrict__ Win1, const float *__restrict__ Wz1,
                             const float *__restrict__ W01,  const float *__restrict__ W11) {
    int idx = blockIdx.x*blockDim.x + threadIdx.x, mlp = blockIdx.y;
    const float *Win = mlp ? Win1 : Win0, *Wz = mlp ? Wz1 : Wz0;
    const float *W0p = mlp ? W01 : W00, *W1p = mlp ? W11 : W10;
    char *out = g_wimg[mlp];
    float v; unsigned off;
    if (idx < 8192) {                       // input chunk: n=128, k=64 (k>=42 zero)
        int n = idx >> 6, k = idx & 63;
        v = (k < 42) ? Win[k*128 + n] : 0.f;
        off = n*WS + k*2;
    } else {
        int e = idx - 8192; if (e >= 9*16384) return;
        int mat = e >> 14, r = e & 16383, n = r >> 7, k = r & 127;
        int blk = mat/3, t = mat%3;
        const float *W = (t==0 ? Wz : t==1 ? W0p : W1p) + blk*16384;
        v = W[k*128 + n];
        unsigned chunk = 1u + (unsigned)mat*2u + (k >= 64 ? 1u : 0u);
        off = chunk*WCHUNK + n*WS + (k & 63)*2;
    }
    __nv_bfloat16 hi = __float2bfloat16(v);
    __nv_bfloat16 lo = __float2bfloat16(v - __bfloat162float(hi));
    *(__nv_bfloat16 *)(out + off) = hi;
    *(__nv_bfloat16 *)(out + WLO + off) = lo;
}

__global__ void setup_kernel(const float *__restrict__ K4, const float *__restrict__ s2i,
                             const float *__restrict__ pix) {
    int r = blockIdx.x*blockDim.x + threadIdx.x;
    if (r >= NRAYS) return;
    float a = K4[0], b = K4[1], c = K4[2], d = K4[3], e = K4[4], f = K4[5];
    float g = K4[6], h = K4[7], i9 = K4[8];
    float A = e*i9-f*h, B = c*h-b*i9, C = b*f-c*e, D = f*g-d*i9, E = a*i9-c*g, F = c*d-a*f;
    float G = d*h-e*g, H = b*g-a*h, I = a*e-b*d;
    float idet = 1.f/(a*A + b*D + c*G);
    float u = pix[2*r], v = pix[2*r+1];
    float cx = (A*u+B*v+C)*idet, cy = (D*u+E*v+F)*idet, cz = (G*u+H*v+I)*idet;
    g_cam[3*r] = cx; g_cam[3*r+1] = cy; g_cam[3*r+2] = cz;
    float dx = s2i[0]*cx+s2i[1]*cy+s2i[2]*cz, dy = s2i[4]*cx+s2i[5]*cy+s2i[6]*cz,
          dz = s2i[8]*cx+s2i[9]*cy+s2i[10]*cz;
    g_dirs[3*r] = dx; g_dirs[3*r+1] = dy; g_dirs[3*r+2] = dz;
    float inv = rsqrtf(dx*dx+dy*dy+dz*dz);
    g_view[3*r] = dx*inv; g_view[3*r+1] = dy*inv; g_view[3*r+2] = dz*inv;
}

__device__ __forceinline__ void storeA(char *sA, int row, int col, float v0, float v1) {
    __nv_bfloat162 hh = __floats2bfloat162_rn(v0, v1);
    __nv_bfloat162 ll = __floats2bfloat162_rn(v0 - __bfloat162float(hh.x), v1 - __bfloat162float(hh.y));
    unsigned off = row*AS + col*2;
    *(unsigned *)(sA + off) = *(unsigned *)&hh;
    *(unsigned *)(sA + ALO + off) = *(unsigned *)&ll;
}

template <bool GAUSS>
__global__ void __launch_bounds__(NT, 1) decode_mma(
        const float *__restrict__ s2i,
        const float *__restrict__ bin, const float *__restrict__ bz,
        const float *__restrict__ b0,  const float *__restrict__ b1,
        const float *__restrict__ Wout,const float *__restrict__ bout) {
    constexpr int S = GAUSS ? NG : SMAIN;
    constexpr int DOUT = GAUSS ? 2 : 4;
    extern __shared__ char dynsm[];
    __shared__ float s_bias[10][128], s_wout[128*4], s_partial[4][128][4], s_f[128][3];
    __shared__ int s_base[128], s_val[128];

    const int tid = threadIdx.x, lane = tid & 31, w = tid >> 5;   // 16 warps
    const int q = lane >> 2, tq = lane & 3, wm = w & 3, wn = w >> 2;  // 4x4 warp grid
    const int n0 = blockIdx.x*128;
    const char *wimg = g_wimg[GAUSS ? 1 : 0];
    char *sW = dynsm, *sA = sW + 2*WCHUNK, *sZ = sA + 2*ALO;
    const unsigned uW = smem_u32(sW), uA = smem_u32(sA), uZ = smem_u32(sZ);

    pf(sW, wimg, WCHUNK, tid);                         // chunk0 (input layer)

    if (tid < 128) {
        s_bias[0][tid] = bin[tid];
#pragma unroll
        for (int blk = 0; blk < 3; blk++) {
            s_bias[1+blk*3+0][tid] = bz[blk*128+tid];
            s_bias[1+blk*3+1][tid] = b0[blk*128+tid];
            s_bias[1+blk*3+2][tid] = b1[blk*128+tid];
        }
    }
    for (int i = tid; i < 128*DOUT; i += NT) s_wout[i] = Wout[i];

    // geometry + features
    if (tid < 128) {
        int p = tid, n = n0+p, r = n/S, s = n - r*S;
        float dpt = GAUSS ? ((float)s + 0.5f)*25.0f : g_dall[n];
        float ptx = s2i[3]  + g_dirs[3*r]*dpt;
        float pty = s2i[7]  + g_dirs[3*r+1]*dpt;
        float ptz = s2i[11] + g_dirs[3*r+2]*dpt;
        float gx = (ptx+51.2f)*(199.0f/102.4f), gy = (pty+51.2f)*(199.0f/102.4f), gz = (ptz+5.0f)*(7.0f/8.0f);
        s_val[p] = (gx>=0.f)&(gx<=199.f)&(gy>=0.f)&(gy<=199.f)&(gz>=0.f)&(gz<=7.f);
        int x0 = min(max((int)floorf(gx),0),198), y0 = min(max((int)floorf(gy),0),198), z0 = min(max((int)floorf(gz),0),6);
        s_f[p][0] = fminf(fmaxf(gx-(float)x0,0.f),1.f);
        s_f[p][1] = fminf(fmaxf(gy-(float)y0,0.f),1.f);
        s_f[p][2] = fminf(fmaxf(gz-(float)z0,0.f),1.f);
        s_base[p] = ((z0*200+x0)*200+y0)*128;
        float f[64];
#pragma unroll
        for (int k = 0; k < 64; k++) f[k] = 0.f;
        f[0] = ptx; f[1] = pty; f[2] = ptz;
        float xyz[3] = {ptx, pty, ptz};
#pragma unroll
        for (int fr = 0; fr < 6; fr++) {
            float sc = 3.14159265358979323846f*(float)(1 << fr);
#pragma unroll
            for (int t = 0; t < 3; t++) {
                float xx = xyz[t]*sc;
                f[3+fr*6+t] = sinf(xx); f[3+fr*6+3+t] = cosf(xx);
            }
        }
        f[39] = g_view[3*r]; f[40] = g_view[3*r+1]; f[41] = g_view[3*r+2];
#pragma unroll
        for (int i = 0; i < 32; i++) storeA(sA, p, 2*i, f[2*i], f[2*i+1]);
    }
    __syncthreads();     // s_val/s_f/s_base visible for gather
    {   // Z gather: channel c, quarter of points per thread group
        int c = tid & 127, p0 = (tid >> 7)*32;
        for (int p = p0; p < p0+32; p++) {
            float zv = 0.f;
            if (s_val[p]) {
                const float *vp = g_vox + s_base[p] + c;
                float fx = s_f[p][0], fy = s_f[p][1], fz = s_f[p][2];
                float ox = 1.f-fx, oy = 1.f-fy, oz = 1.f-fz;
                float c00 = vp[0]*ox + vp[25600]*fx, c01 = vp[128]*ox + vp[25728]*fx;
                float c10 = vp[5120000]*ox + vp[5145600]*fx, c11 = vp[5120128]*ox + vp[5145728]*fx;
                zv = (c00*oy + c01*fy)*oz + (c10*oy + c11*fy)*fz;
            }
            __nv_bfloat16 zh = __float2bfloat16(zv);
            __nv_bfloat16 zl = __float2bfloat16(zv - __bfloat162float(zh));
            unsigned off = p*AS + c*2;
            *(__nv_bfloat16 *)(sZ + off) = zh;
            *(__nv_bfloat16 *)(sZ + ALO + off) = zl;
        }
    }

    float h[2][4][4], acc[2][4][4];
    int cur = 0;

    // input layer: h = x @ Win + bin   (K=64, chunk0 in buf0)
    BND();
    pf(sW + WCHUNK, wimg + WCHUNK, WCHUNK, tid);       // chunk1 -> buf1
#pragma unroll
    for (int mt = 0; mt < 2; mt++)
#pragma unroll
        for (int nt = 0; nt < 4; nt++)
#pragma unroll
            for (int c = 0; c < 4; c++) acc[mt][nt][c] = 0.f;
    mma_half(acc, uA, uW, 0, lane, wm, wn);
    cur = 1;
#pragma unroll
    for (int mt = 0; mt < 2; mt++)
#pragma unroll
        for (int nt = 0; nt < 4; nt++)
#pragma unroll
            for (int c = 0; c < 4; c++)
                h[mt][nt][c] = acc[mt][nt][c] + s_bias[0][wn*32 + nt*8 + tq*2 + (c & 1)];

    for (int st = 0; st < 9; st++) {
        int t = st % 3;
        unsigned src = (t == 0) ? uZ : uA;
#pragma unroll
        for (int mt = 0; mt < 2; mt++)
#pragma unroll
            for (int nt = 0; nt < 4; nt++)
#pragma unroll
                for (int c = 0; c < 4; c++) acc[mt][nt][c] = 0.f;
        // half 0
        BND();
        if (cur + 1 < NCHUNK) pf(sW + ((cur+1)&1)*WCHUNK, wimg + (cur+1)*WCHUNK, WCHUNK, tid);
        mma_half(acc, src, uW + (cur&1)*WCHUNK, 0, lane, wm, wn);
        cur++;
        // half 1
        BND();
        if (cur + 1 < NCHUNK) pf(sW + ((cur+1)&1)*WCHUNK, wimg + (cur+1)*WCHUNK, WCHUNK, tid);
        mma_half(acc, src, uW + (cur&1)*WCHUNK, 64, lane, wm, wn);
        cur++;
        __syncthreads();          // all warps done reading A/Z/W before A overwrite
        int bi = 1 + (st/3)*3 + t;
#pragma unroll
        for (int mt = 0; mt < 2; mt++)
#pragma unroll
            for (int nt = 0; nt < 4; nt++) {
                int colb = wn*32 + nt*8 + tq*2;
                float bb0 = s_bias[bi][colb], bb1 = s_bias[bi][colb+1];
                if (t == 1) {     // net = D + b0 ; A = split(relu(net)) ; h unchanged
                    float n0v = acc[mt][nt][0] + bb0, n1v = acc[mt][nt][1] + bb1;
                    float n2v = acc[mt][nt][2] + bb0, n3v = acc[mt][nt][3] + bb1;
                    storeA(sA, wm*32 + mt*16 + q,     colb, fmaxf(n0v,0.f), fmaxf(n1v,0.f));
                    storeA(sA, wm*32 + mt*16 + q + 8, colb, fmaxf(n2v,0.f), fmaxf(n3v,0.f));
                } else {          // h += D + b ; if t==0: A = split(relu(h))
                    h[mt][nt][0] += acc[mt][nt][0] + bb0;
                    h[mt][nt][1] += acc[mt][nt][1] + bb1;
                    h[mt][nt][2] += acc[mt][nt][2] + bb0;
                    h[mt][nt][3] += acc[mt][nt][3] + bb1;
                    if (t == 0) {
                        storeA(sA, wm*32 + mt*16 + q,     colb, fmaxf(h[mt][nt][0],0.f), fmaxf(h[mt][nt][1],0.f));
                        storeA(sA, wm*32 + mt*16 + q + 8, colb, fmaxf(h[mt][nt][2],0.f), fmaxf(h[mt][nt][3],0.f));
                    }
                }
            }
        __syncthreads();
    }

    // final: out = relu(h) @ Wout (+bout later), quad reduce then 4-group reduce
#pragma unroll
    for (int mt = 0; mt < 2; mt++)
#pragma unroll
        for (int half = 0; half < 2; half++) {
            int row = wm*32 + mt*16 + q + half*8;
            float po[4] = {0,0,0,0};
#pragma unroll
            for (int nt = 0; nt < 4; nt++) {
                int colb = wn*32 + nt*8 + tq*2;
                float r0v = fmaxf(h[mt][nt][half*2+0], 0.f);
                float r1v = fmaxf(h[mt][nt][half*2+1], 0.f);
#pragma unroll
                for (int o = 0; o < DOUT; o++)
                    po[o] += r0v*s_wout[colb*DOUT+o] + r1v*s_wout[(colb+1)*DOUT+o];
            }
#pragma unroll
            for (int o = 0; o < DOUT; o++) {
                po[o] += __shfl_xor_sync(0xffffffffu, po[o], 1);
                po[o] += __shfl_xor_sync(0xffffffffu, po[o], 2);
            }
            if (tq == 0)
#pragma unroll
                for (int o = 0; o < DOUT; o++) s_partial[wn][row][o] = po[o];
        }
    __syncthreads();
    if (tid < 128)
#pragma unroll
        for (int o = 0; o < DOUT; o++)
            (GAUSS ? g_outg : g_outm)[(n0+tid)*DOUT+o] =
                s_partial[0][tid][o] + s_partial[1][tid][o] +
                s_partial[2][tid][o] + s_partial[3][tid][o] + bout[o];
}

__global__ void gprep_kernel() {
    int r = blockIdx.x*blockDim.x + threadIdx.x;
    if (r >= NRAYS) return;
    float m[NG], sd[NG], d[SMAIN];
#pragma unroll
    for (int g = 0; g < NG; g++) {
        float o0 = g_outg[(r*NG+g)*2], o1 = g_outg[(r*NG+g)*2+1];
        m[g] = ((float)g+0.5f)*25.f + tanhf(o0)*12.5f;
        sd[g] = 1.f/(1.f+expf(-o1))*5.f + 0.001f;
        g_means[r*NG+g] = m[g]; g_stds[r*NG+g] = sd[g];
    }
    for (int i = 0; i < 32; i++) d[i] = 0.5f + (float)i*(99.5f/31.f);
    int idx = 32;
    for (int g = 0; g < NG; g++)
        for (int jj = 0; jj < 8; jj++)
            d[idx++] = m[g] + (-1.f + (float)jj*(2.f/7.f))*2.f*sd[g];
    for (int i = 0; i < SMAIN; i++) d[i] = fminf(fmaxf(d[i], 0.01f), 100.f);
    for (int i = 1; i < SMAIN; i++) {
        float v = d[i]; int k = i-1;
        while (k >= 0 && d[k] > v) { d[k+1] = d[k]; k--; }
        d[k+1] = v;
    }
    for (int i = 0; i < SMAIN; i++) g_dall[r*SMAIN+i] = d[i];
}

__device__ __forceinline__ void samp_img(const float *__restrict__ img, float u, float v, float *o3) {
    float x0f = fminf(fmaxf(floorf(u), 0.f), (float)(IMGW-2));
    float y0f = fminf(fmaxf(floorf(v), 0.f), (float)(IMGH-2));
    int x0 = (int)x0f, y0 = (int)y0f;
    float fx = fminf(fmaxf(u-x0f,0.f),1.f), fy = fminf(fmaxf(v-y0f,0.f),1.f);
    float w00 = (1.f-fx)*(1.f-fy), w10 = fx*(1.f-fy), w01 = (1.f-fx)*fy, w11 = fx*fy;
#pragma unroll
    for (int c = 0; c < 3; c++) {
        int b = c*IMGH*IMGW + y0*IMGW + x0;
        o3[c] = img[b]*w00 + img[b+1]*w10 + img[b+IMGW]*w01 + img[b+IMGW+1]*w11;
    }
}

__global__ void render_kernel(const float *__restrict__ src, const float *__restrict__ tgt,
                              const float *__restrict__ K4, const float *__restrict__ s2t,
                              const float *__restrict__ pix, float *__restrict__ dout) {
    int r = blockIdx.x*blockDim.x + threadIdx.x;
    if (r >= NRAYS) return;
    const float EPSf = 1e-6f;
    float d[SMAIN], w[SMAIN], q[SMAIN];
    for (int s = 0; s < SMAIN; s++) d[s] = g_dall[r*SMAIN+s];
    float T = 1.f, depth = 0.f, c0 = 0.f, c1 = 0.f, c2 = 0.f, wsum = 0.f;
    for (int s = 0; s < SMAIN; s++) {
        float4 o = reinterpret_cast<const float4 *>(g_outm)[r*SMAIN+s];
        float delta = (s < SMAIN-1) ? (d[s+1]-d[s]) : 1e10f;
        float alpha = 1.f - expf(-fmaxf(o.x, 0.f)*delta);
        float ww = alpha*T; T *= (1.f - alpha + 1e-10f);
        w[s] = ww; wsum += ww; depth += ww*d[s];
        c0 += ww/(1.f+expf(-o.y)); c1 += ww/(1.f+expf(-o.z)); c2 += ww/(1.f+expf(-o.w));
    }
    float m[NG], sd[NG], ls[NG];
#pragma unroll
    for (int g = 0; g < NG; g++) { m[g] = g_means[r*NG+g]; sd[g] = g_stds[r*NG+g]; ls[g] = logf(sd[g]); }
    float qsum = 0.f;
    for (int s = 0; s < SMAIN; s++) {
        float qq = 0.f;
#pragma unroll
        for (int g = 0; g < NG; g++) {
            float t = (d[s]-m[g])/sd[g];
            qq += expf(-0.5f*t*t - ls[g]);
        }
        q[s] = qq*0.25f; qsum += q[s];
    }
    float kl = 0.f;
    for (int s = 0; s < SMAIN; s++) {
        float pw = w[s]/(wsum+EPSf), qn = q[s]/(qsum+EPSf);
        kl += pw*(logf(pw+EPSf) - logf(qn+EPSf));
    }
    float d2c = 1e30f;
#pragma unroll
    for (int g = 0; g < NG; g++) d2c = fminf(d2c, fabsf(m[g]-depth));
    float sc[3]; samp_img(src, pix[2*r], pix[2*r+1], sc);
    float closs = fabsf(sc[0]-c0) + fabsf(sc[1]-c1) + fabsf(sc[2]-c2);
    float cx = g_cam[3*r]*depth, cy = g_cam[3*r+1]*depth, cz = g_cam[3*r+2]*depth;
    float tx = s2t[0]*cx+s2t[1]*cy+s2t[2]*cz+s2t[3];
    float ty = s2t[4]*cx+s2t[5]*cy+s2t[6]*cz+s2t[7];
    float tz = s2t[8]*cx+s2t[9]*cy+s2t[10]*cz+s2t[11];
    float pxp = K4[0]*tx+K4[1]*ty+K4[2]*tz, pyp = K4[3]*tx+K4[4]*ty+K4[5]*tz, pzp = K4[6]*tx+K4[7]*ty+K4[8]*tz;
    float tc[3]; samp_img(tgt, pxp/(pzp+EPSf), pyp/(pzp+EPSf), tc);
    float mask = (depth < 30.f) ? 1.f : 0.f;
    g_kl[r] = kl; g_d2c[r] = d2c; g_colL[r] = closs;
    g_rn[r] = mask*(fabsf(tc[0]-sc[0]) + fabsf(tc[1]-sc[1]) + fabsf(tc[2]-sc[2]))*(1.f/3.f);
    g_rd[r] = mask;
    dout[1+r] = depth;
    dout[1+NRAYS+3*r+0] = c0; dout[1+NRAYS+3*r+1] = c1; dout[1+NRAYS+3*r+2] = c2;
}

__global__ void reduce_kernel(float *__restrict__ dout) {
    __shared__ float sm[5][256];
    int t = threadIdx.x;
    float a[5] = {0,0,0,0,0};
    for (int r = t; r < NRAYS; r += 256) {
        a[0] += g_kl[r]; a[1] += g_d2c[r]; a[2] += g_colL[r]; a[3] += g_rn[r]; a[4] += g_rd[r];
    }
    for (int c = 0; c < 5; c++) sm[c][t] = a[c];
    __syncthreads();
    for (int s = 128; s > 0; s >>= 1) {
        if (t < s) for (int c = 0; c < 5; c++) sm[c][t] += sm[c][t+s];
        __syncthreads();
    }
    if (t == 0)
        dout[0] = sm[0][0]*(1.f/NRAYS) + 0.01f*sm[1][0]*(1.f/NRAYS) +
                  sm[2][0]*(1.f/(3.f*NRAYS)) + sm[3][0]/(sm[4][0]+1e-6f);
}

extern "C" void kernel_launch(void* const* d_in, const int* in_sizes, int n_in,
                              void* d_out, int out_size) {
    const float *bev = (const float *)d_in[0];
    const float *src = (const float *)d_in[1];
    const float *tgt = (const float *)d_in[2];
    const float *K4  = (const float *)d_in[3];
    const float *s2i = (const float *)d_in[4];
    const float *s2t = (const float *)d_in[5];
    const float *pix = (const float *)d_in[6];
    const float *const *m1 = (const float *const *)&d_in[7];
    const float *const *m2 = (const float *const *)&d_in[17];
    float *dout = (float *)d_out;

    cudaFuncSetAttribute(decode_mma<true>,  cudaFuncAttributeMaxDynamicSharedMemorySize, DYNSM);
    cudaFuncSetAttribute(decode_mma<false>, cudaFuncAttributeMaxDynamicSharedMemorySize, DYNSM);

    transpose_kernel<<<dim3(7,4,1600), dim3(32,8)>>>(bev);
    wprep_kernel<<<dim3(608,2), 256>>>(m1[0], m1[2], m1[4], m1[6], m2[0], m2[2], m2[4], m2[6]);
    setup_kernel<<<32, 128>>>(K4, s2i, pix);
    decode_mma<true><<<NRAYS*NG/128, NT, DYNSM>>>(s2i, m2[1], m2[3], m2[5], m2[7], m2[8], m2[9]);
    gprep_kernel<<<64, 64>>>();
    decode_mma<false><<<NRAYS*SMAIN/128, NT, DYNSM>>>(s2i, m1[1], m1[3], m1[5], m1[7], m1[8], m1[9]);
    render_kernel<<<64, 64>>>(src, tgt, K4, s2t, pix, dout);
    reduce_kernel<<<1, 256>>>(dout);
}

// round 16
// speedup vs baseline: 3.8064x; 1.0373x over previous
#include <cuda_runtime.h>
#include <cuda_bf16.h>
typedef unsigned long long u64;
#define NRAYS 4096
#define SMAIN 64
#define NG 4
#define IMGH 900
#define IMGW 1600

// tile geometry
#define AS 272            // A/Z row stride bytes (128 bf16 + pad, 16B aligned)
#define ALO 34816         // lo offset within A/Z tile (128*272)
#define WS 144            // W half-row stride bytes (64 bf16 + pad)
#define WLO 18432         // lo offset within W half (128*144)
#define WCHUNK 36864      // one half-layer image (hi+lo)
#define NCHUNK 19         // 1 input + 9 layers * 2 halves
#define DYNSM (2*WCHUNK + 2*(2*ALO))   // 212992
#define NT 512            // decode threads

__device__ __align__(16) float g_vox[8*200*200*128];
__device__ float g_dirs[NRAYS*3], g_view[NRAYS*3], g_cam[NRAYS*3];
__device__ float g_outg[NRAYS*NG*2], g_means[NRAYS*NG], g_stds[NRAYS*NG];
__device__ float g_dall[NRAYS*SMAIN];
__device__ __align__(16) float g_outm[NRAYS*SMAIN*4];
__device__ float g_kl[NRAYS], g_d2c[NRAYS], g_colL[NRAYS], g_rn[NRAYS], g_rd[NRAYS];
__device__ __align__(16) char g_wimg[2][NCHUNK*WCHUNK];

__device__ __forceinline__ unsigned smem_u32(const void *p) {
    unsigned a; asm("{ .reg .u64 t; cvta.to.shared.u64 t, %1; cvt.u32.u64 %0, t; }":"=r"(a):"l"(p)); return a;
}
__device__ __forceinline__ void ldm4(unsigned *r, unsigned a) {
    asm volatile("ldmatrix.sync.aligned.m8n8.x4.shared.b16 {%0,%1,%2,%3},[%4];"
        :"=r"(r[0]),"=r"(r[1]),"=r"(r[2]),"=r"(r[3]):"r"(a));
}
__device__ __forceinline__ void mma16816(float *d, const unsigned *a, const unsigned *b) {
    asm volatile("mma.sync.aligned.m16n8k16.row.col.f32.bf16.bf16.f32 "
        "{%0,%1,%2,%3},{%4,%5,%6,%7},{%8,%9},{%0,%1,%2,%3};"
        :"+f"(d[0]),"+f"(d[1]),"+f"(d[2]),"+f"(d[3])
        :"r"(a[0]),"r"(a[1]),"r"(a[2]),"r"(a[3]),"r"(b[0]),"r"(b[1]));
}
__device__ __forceinline__ void pf(const void *sdst, const char *g, int bytes, int j) {
    unsigned sa = smem_u32(sdst);
    for (int off = j*16; off < bytes; off += NT*16)
        asm volatile("cp.async.cg.shared.global [%0], [%1], 16;" :: "r"(sa+off), "l"(g+off));
    asm volatile("cp.async.commit_group;" ::: "memory");
}
#define BND() { asm volatile("cp.async.wait_group 0;" ::: "memory"); __syncthreads(); }

// 4 k16-steps of the 3-pass split MMA for one 32x32 warp tile.
__device__ __forceinline__ void mma_half(float acc[2][4][4], unsigned src, unsigned wb,
                                         int kbase, int lane, int wm, int wn) {
#pragma unroll
    for (int ks = 0; ks < 4; ks++) {
        int kg = kbase + ks*16;
        unsigned ah[2][4], al[2][4];
#pragma unroll
        for (int mt = 0; mt < 2; mt++) {
            unsigned ra = src + (wm*32 + mt*16 + (lane & 15))*AS + ((lane >> 4)*8 + kg)*2;
            ldm4(ah[mt], ra); ldm4(al[mt], ra + ALO);
        }
#pragma unroll
        for (int ntp = 0; ntp < 2; ntp++) {
            unsigned rb = wb + (wn*32 + ntp*16 + (lane>>4)*8 + (lane&7))*WS
                             + (((lane>>3)&1)*8 + ks*16)*2;
            unsigned bh[4], bl[4];
            ldm4(bh, rb); ldm4(bl, rb + WLO);
#pragma unroll
            for (int sub = 0; sub < 2; sub++) {
                int nt = ntp*2 + sub;
#pragma unroll
                for (int mt = 0; mt < 2; mt++) {
                    mma16816(acc[mt][nt], ah[mt], bh + sub*2);
                    mma16816(acc[mt][nt], ah[mt], bl + sub*2);
                    mma16816(acc[mt][nt], al[mt], bh + sub*2);
                }
            }
        }
    }
}

// ---- fused prep: transpose (blocks 0..44799) + wprep (..46015) + setup (..46031) ----
__global__ void prep_kernel(const float *__restrict__ bev,
                            const float *__restrict__ K4, const float *__restrict__ s2i,
                            const float *__restrict__ pix,
                            const float *__restrict__ Win0, const float *__restrict__ Wz0,
                            const float *__restrict__ W00,  const float *__restrict__ W10,
                            const float *__restrict__ Win1, const float *__restrict__ Wz1,
                            const float *__restrict__ W01,  const float *__restrict__ W11) {
    __shared__ float tile[32][33];
    int b = blockIdx.x, tid = threadIdx.x;
    if (b < 44800) {
        int bx = b % 7, rem = b / 7, by = rem % 4, dh = rem / 4;
        int d = dh/200, h = dh - d*200;
        int w0 = bx*32, c0 = by*32, tx = tid & 31, ty = tid >> 5;
#pragma unroll
        for (int i = 0; i < 32; i += 8) {
            int c = c0+ty+i, w = w0+tx;
            if (w < 200) tile[ty+i][tx] = bev[(c*8+d)*40000 + h*200 + w];
        }
        __syncthreads();
#pragma unroll
        for (int i = 0; i < 32; i += 8) {
            int w = w0+ty+i, c = c0+tx;
            if (w < 200) g_vox[((d*200+h)*200+w)*128 + c] = tile[tx][ty+i];
        }
    } else if (b < 46016) {
        int b2 = b - 44800, mlp = b2 & 1, idx = (b2 >> 1)*256 + tid;
        const float *Win = mlp ? Win1 : Win0, *Wz = mlp ? Wz1 : Wz0;
        const float *W0p = mlp ? W01 : W00, *W1p = mlp ? W11 : W10;
        char *out = g_wimg[mlp];
        float v; unsigned off;
        if (idx < 8192) {
            int n = idx >> 6, k = idx & 63;
            v = (k < 42) ? Win[k*128 + n] : 0.f;
            off = n*WS + k*2;
        } else {
            int e = idx - 8192; if (e >= 9*16384) return;
            int mat = e >> 14, r = e & 16383, n = r >> 7, k = r & 127;
            int blk = mat/3, t = mat%3;
            const float *W = (t==0 ? Wz : t==1 ? W0p : W1p) + blk*16384;
            v = W[k*128 + n];
            unsigned chunk = 1u + (unsigned)mat*2u + (k >= 64 ? 1u : 0u);
            off = chunk*WCHUNK + n*WS + (k & 63)*2;
        }
        __nv_bfloat16 hi = __float2bfloat16(v);
        __nv_bfloat16 lo = __float2bfloat16(v - __bfloat162float(hi));
        *(__nv_bfloat16 *)(out + off) = hi;
        *(__nv_bfloat16 *)(out + WLO + off) = lo;
    } else {
        int r = (b - 46016)*256 + tid;
        if (r >= NRAYS) return;
        float a = K4[0], bb = K4[1], c = K4[2], d = K4[3], e = K4[4], f = K4[5];
        float g = K4[6], h = K4[7], i9 = K4[8];
        float A = e*i9-f*h, B = c*h-bb*i9, C = bb*f-c*e, D = f*g-d*i9, E = a*i9-c*g, F = c*d-a*f;
        float G = d*h-e*g, H = bb*g-a*h, I = a*e-bb*d;
        float idet = 1.f/(a*A + bb*D + c*G);
        float u = pix[2*r], v = pix[2*r+1];
        float cx = (A*u+B*v+C)*idet, cy = (D*u+E*v+F)*idet, cz = (G*u+H*v+I)*idet;
        g_cam[3*r] = cx; g_cam[3*r+1] = cy; g_cam[3*r+2] = cz;
        float dx = s2i[0]*cx+s2i[1]*cy+s2i[2]*cz, dy = s2i[4]*cx+s2i[5]*cy+s2i[6]*cz,
              dz = s2i[8]*cx+s2i[9]*cy+s2i[10]*cz;
        g_dirs[3*r] = dx; g_dirs[3*r+1] = dy; g_dirs[3*r+2] = dz;
        float inv = rsqrtf(dx*dx+dy*dy+dz*dz);
        g_view[3*r] = dx*inv; g_view[3*r+1] = dy*inv; g_view[3*r+2] = dz*inv;
    }
}

__device__ __forceinline__ void storeA(char *sA, int row, int col, float v0, float v1) {
    __nv_bfloat162 hh = __floats2bfloat162_rn(v0, v1);
    __nv_bfloat162 ll = __floats2bfloat162_rn(v0 - __bfloat162float(hh.x), v1 - __bfloat162float(hh.y));
    unsigned off = row*AS + col*2;
    *(unsigned *)(sA + off) = *(unsigned *)&hh;
    *(unsigned *)(sA + ALO + off) = *(unsigned *)&ll;
}

template <bool GAUSS>
__global__ void __launch_bounds__(NT, 1) decode_mma(
        const float *__restrict__ s2i,
        const float *__restrict__ bin, const float *__restrict__ bz,
        const float *__restrict__ b0,  const float *__restrict__ b1,
        const float *__restrict__ Wout,const float *__restrict__ bout) {
    constexpr int S = GAUSS ? NG : SMAIN;
    constexpr int DOUT = GAUSS ? 2 : 4;
    extern __shared__ char dynsm[];
    __shared__ float s_bias[10][128], s_wout[128*4], s_partial[4][128][4], s_f[128][3];
    __shared__ int s_base[128], s_val[128];

    const int tid = threadIdx.x, lane = tid & 31, w = tid >> 5;   // 16 warps
    const int q = lane >> 2, tq = lane & 3, wm = w & 3, wn = w >> 2;  // 4x4 warp grid
    const int n0 = blockIdx.x*128;
    const char *wimg = g_wimg[GAUSS ? 1 : 0];
    char *sW = dynsm, *sA = sW + 2*WCHUNK, *sZ = sA + 2*ALO;
    const unsigned uW = smem_u32(sW), uA = smem_u32(sA), uZ = smem_u32(sZ);

    pf(sW, wimg, WCHUNK, tid);                         // chunk0 (input layer)

    if (tid < 128) {
        s_bias[0][tid] = bin[tid];
#pragma unroll
        for (int blk = 0; blk < 3; blk++) {
            s_bias[1+blk*3+0][tid] = bz[blk*128+tid];
            s_bias[1+blk*3+1][tid] = b0[blk*128+tid];
            s_bias[1+blk*3+2][tid] = b1[blk*128+tid];
        }
    }
    for (int i = tid; i < 128*DOUT; i += NT) s_wout[i] = Wout[i];

    // geometry + features
    if (tid < 128) {
        int p = tid, n = n0+p, r = n/S, s = n - r*S;
        float dpt = GAUSS ? ((float)s + 0.5f)*25.0f : g_dall[n];
        float ptx = s2i[3]  + g_dirs[3*r]*dpt;
        float pty = s2i[7]  + g_dirs[3*r+1]*dpt;
        float ptz = s2i[11] + g_dirs[3*r+2]*dpt;
        float gx = (ptx+51.2f)*(199.0f/102.4f), gy = (pty+51.2f)*(199.0f/102.4f), gz = (ptz+5.0f)*(7.0f/8.0f);
        s_val[p] = (gx>=0.f)&(gx<=199.f)&(gy>=0.f)&(gy<=199.f)&(gz>=0.f)&(gz<=7.f);
        int x0 = min(max((int)floorf(gx),0),198), y0 = min(max((int)floorf(gy),0),198), z0 = min(max((int)floorf(gz),0),6);
        s_f[p][0] = fminf(fmaxf(gx-(float)x0,0.f),1.f);
        s_f[p][1] = fminf(fmaxf(gy-(float)y0,0.f),1.f);
        s_f[p][2] = fminf(fmaxf(gz-(float)z0,0.f),1.f);
        s_base[p] = ((z0*200+x0)*200+y0)*128;
        float f[64];
#pragma unroll
        for (int k = 0; k < 64; k++) f[k] = 0.f;
        f[0] = ptx; f[1] = pty; f[2] = ptz;
        float xyz[3] = {ptx, pty, ptz};
#pragma unroll
        for (int fr = 0; fr < 6; fr++) {
            float sc = 3.14159265358979323846f*(float)(1 << fr);
#pragma unroll
            for (int t = 0; t < 3; t++) {
                float xx = xyz[t]*sc;
                f[3+fr*6+t] = sinf(xx); f[3+fr*6+3+t] = cosf(xx);
            }
        }
        f[39] = g_view[3*r]; f[40] = g_view[3*r+1]; f[41] = g_view[3*r+2];
#pragma unroll
        for (int i = 0; i < 32; i++) storeA(sA, p, 2*i, f[2*i], f[2*i+1]);
    }
    __syncthreads();     // s_val/s_f/s_base visible for gather
    {   // Z gather
        int c = tid & 127, p0 = (tid >> 7)*32;
        for (int p = p0; p < p0+32; p++) {
            float zv = 0.f;
            if (s_val[p]) {
                const float *vp = g_vox + s_base[p] + c;
                float fx = s_f[p][0], fy = s_f[p][1], fz = s_f[p][2];
                float ox = 1.f-fx, oy = 1.f-fy, oz = 1.f-fz;
                float c00 = vp[0]*ox + vp[25600]*fx, c01 = vp[128]*ox + vp[25728]*fx;
                float c10 = vp[5120000]*ox + vp[5145600]*fx, c11 = vp[5120128]*ox + vp[5145728]*fx;
                zv = (c00*oy + c01*fy)*oz + (c10*oy + c11*fy)*fz;
            }
            __nv_bfloat16 zh = __float2bfloat16(zv);
            __nv_bfloat16 zl = __float2bfloat16(zv - __bfloat162float(zh));
            unsigned off = p*AS + c*2;
            *(__nv_bfloat16 *)(sZ + off) = zh;
            *(__nv_bfloat16 *)(sZ + ALO + off) = zl;
        }
    }

    float h[2][4][4], acc[2][4][4];
    int cur = 0;

    // input layer: h = x @ Win + bin   (K=64, chunk0 in buf0)
    BND();
    pf(sW + WCHUNK, wimg + WCHUNK, WCHUNK, tid);       // chunk1 -> buf1
#pragma unroll
    for (int mt = 0; mt < 2; mt++)
#pragma unroll
        for (int nt = 0; nt < 4; nt++)
#pragma unroll
            for (int c = 0; c < 4; c++) acc[mt][nt][c] = 0.f;
    mma_half(acc, uA, uW, 0, lane, wm, wn);
    cur = 1;
#pragma unroll
    for (int mt = 0; mt < 2; mt++)
#pragma unroll
        for (int nt = 0; nt < 4; nt++)
#pragma unroll
            for (int c = 0; c < 4; c++)
                h[mt][nt][c] = acc[mt][nt][c] + s_bias[0][wn*32 + nt*8 + tq*2 + (c & 1)];

    for (int st = 0; st < 9; st++) {
        int t = st % 3;
        unsigned src = (t == 0) ? uZ : uA;
#pragma unroll
        for (int mt = 0; mt < 2; mt++)
#pragma unroll
            for (int nt = 0; nt < 4; nt++)
#pragma unroll
                for (int c = 0; c < 4; c++) acc[mt][nt][c] = 0.f;
        // half 0  (BND's syncthreads also orders previous epilogue's A writes)
        BND();
        if (cur + 1 < NCHUNK) pf(sW + ((cur+1)&1)*WCHUNK, wimg + (cur+1)*WCHUNK, WCHUNK, tid);
        mma_half(acc, src, uW + (cur&1)*WCHUNK, 0, lane, wm, wn);
        cur++;
        // half 1
        BND();
        if (cur + 1 < NCHUNK) pf(sW + ((cur+1)&1)*WCHUNK, wimg + (cur+1)*WCHUNK, WCHUNK, tid);
        mma_half(acc, src, uW + (cur&1)*WCHUNK, 64, lane, wm, wn);
        cur++;
        // Only t==1 stages overwrite A rows they read this stage; sync just the
        // 4 warps (one wm group) that own those rows. t==0 reads Z (A write is
        // ordered by next BND); t==2 writes nothing to smem.
        if (t == 1)
            asm volatile("bar.sync %0, 128;" :: "r"(1 + wm) : "memory");
        int bi = 1 + (st/3)*3 + t;
#pragma unroll
        for (int mt = 0; mt < 2; mt++)
#pragma unroll
            for (int nt = 0; nt < 4; nt++) {
                int colb = wn*32 + nt*8 + tq*2;
                float bb0 = s_bias[bi][colb], bb1 = s_bias[bi][colb+1];
                if (t == 1) {     // net = D + b0 ; A = split(relu(net)) ; h unchanged
                    float n0v = acc[mt][nt][0] + bb0, n1v = acc[mt][nt][1] + bb1;
                    float n2v = acc[mt][nt][2] + bb0, n3v = acc[mt][nt][3] + bb1;
                    storeA(sA, wm*32 + mt*16 + q,     colb, fmaxf(n0v,0.f), fmaxf(n1v,0.f));
                    storeA(sA, wm*32 + mt*16 + q + 8, colb, fmaxf(n2v,0.f), fmaxf(n3v,0.f));
                } else {          // h += D + b ; if t==0: A = split(relu(h))
                    h[mt][nt][0] += acc[mt][nt][0] + bb0;
                    h[mt][nt][1] += acc[mt][nt][1] + bb1;
                    h[mt][nt][2] += acc[mt][nt][2] + bb0;
                    h[mt][nt][3] += acc[mt][nt][3] + bb1;
                    if (t == 0) {
                        storeA(sA, wm*32 + mt*16 + q,     colb, fmaxf(h[mt][nt][0],0.f), fmaxf(h[mt][nt][1],0.f));
                        storeA(sA, wm*32 + mt*16 + q + 8, colb, fmaxf(h[mt][nt][2],0.f), fmaxf(h[mt][nt][3],0.f));
                    }
                }
            }
        // no trailing sync: next stage's BND orders these A writes
    }

    // final: out = relu(h) @ Wout (+bout later)
#pragma unroll
    for (int mt = 0; mt < 2; mt++)
#pragma unroll
        for (int half = 0; half < 2; half++) {
            int row = wm*32 + mt*16 + q + half*8;
            float po[4] = {0,0,0,0};
#pragma unroll
            for (int nt = 0; nt < 4; nt++) {
                int colb = wn*32 + nt*8 + tq*2;
                float r0v = fmaxf(h[mt][nt][half*2+0], 0.f);
                float r1v = fmaxf(h[mt][nt][half*2+1], 0.f);
#pragma unroll
                for (int o = 0; o < DOUT; o++)
                    po[o] += r0v*s_wout[colb*DOUT+o] + r1v*s_wout[(colb+1)*DOUT+o];
            }
#pragma unroll
            for (int o = 0; o < DOUT; o++) {
                po[o] += __shfl_xor_sync(0xffffffffu, po[o], 1);
                po[o] += __shfl_xor_sync(0xffffffffu, po[o], 2);
            }
            if (tq == 0)
#pragma unroll
                for (int o = 0; o < DOUT; o++) s_partial[wn][row][o] = po[o];
        }
    __syncthreads();
    if (tid < 128)
#pragma unroll
        for (int o = 0; o < DOUT; o++)
            (GAUSS ? g_outg : g_outm)[(n0+tid)*DOUT+o] =
                s_partial[0][tid][o] + s_partial[1][tid][o] +
                s_partial[2][tid][o] + s_partial[3][tid][o] + bout[o];
}

__global__ void gprep_kernel() {
    int r = blockIdx.x*blockDim.x + threadIdx.x;
    if (r >= NRAYS) return;
    float m[NG], sd[NG], d[SMAIN];
#pragma unroll
    for (int g = 0; g < NG; g++) {
        float o0 = g_outg[(r*NG+g)*2], o1 = g_outg[(r*NG+g)*2+1];
        m[g] = ((float)g+0.5f)*25.f + tanhf(o0)*12.5f;
        sd[g] = 1.f/(1.f+expf(-o1))*5.f + 0.001f;
        g_means[r*NG+g] = m[g]; g_stds[r*NG+g] = sd[g];
    }
#pragma unroll
    for (int i = 0; i < 32; i++) d[i] = 0.5f + (float)i*(99.5f/31.f);
#pragma unroll
    for (int g = 0; g < NG; g++)
#pragma unroll
        for (int jj = 0; jj < 8; jj++)
            d[32 + g*8 + jj] = m[g] + (-1.f + (float)jj*(2.f/7.f))*2.f*sd[g];
#pragma unroll
    for (int i = 0; i < SMAIN; i++) d[i] = fminf(fmaxf(d[i], 0.01f), 100.f);
    // bitonic sort network: static indices -> registers (no local memory)
#pragma unroll
    for (int k = 2; k <= 64; k <<= 1)
#pragma unroll
        for (int j = k >> 1; j > 0; j >>= 1)
#pragma unroll
            for (int i = 0; i < 64; i++) {
                int l = i ^ j;
                if (l > i) {
                    bool up = ((i & k) == 0);
                    float a = d[i], b = d[l];
                    bool sw = up ? (a > b) : (a < b);
                    if (sw) { d[i] = b; d[l] = a; }
                }
            }
#pragma unroll
    for (int i = 0; i < SMAIN; i++) g_dall[r*SMAIN+i] = d[i];
}

__device__ __forceinline__ void samp_img(const float *__restrict__ img, float u, float v, float *o3) {
    float x0f = fminf(fmaxf(floorf(u), 0.f), (float)(IMGW-2));
    float y0f = fminf(fmaxf(floorf(v), 0.f), (float)(IMGH-2));
    int x0 = (int)x0f, y0 = (int)y0f;
    float fx = fminf(fmaxf(u-x0f,0.f),1.f), fy = fminf(fmaxf(v-y0f,0.f),1.f);
    float w00 = (1.f-fx)*(1.f-fy), w10 = fx*(1.f-fy), w01 = (1.f-fx)*fy, w11 = fx*fy;
#pragma unroll
    for (int c = 0; c < 3; c++) {
        int b = c*IMGH*IMGW + y0*IMGW + x0;
        o3[c] = img[b]*w00 + img[b+1]*w10 + img[b+IMGW]*w01 + img[b+IMGW+1]*w11;
    }
}

__global__ void render_kernel(const float *__restrict__ src, const float *__restrict__ tgt,
                              const float *__restrict__ K4, const float *__restrict__ s2t,
                              const float *__restrict__ pix, float *__restrict__ dout) {
    int r = blockIdx.x*blockDim.x + threadIdx.x;
    if (r >= NRAYS) return;
    const float EPSf = 1e-6f;
    float d[SMAIN], w[SMAIN], q[SMAIN];
    for (int s = 0; s < SMAIN; s++) d[s] = g_dall[r*SMAIN+s];
    float T = 1.f, depth = 0.f, c0 = 0.f, c1 = 0.f, c2 = 0.f, wsum = 0.f;
    for (int s = 0; s < SMAIN; s++) {
        float4 o = reinterpret_cast<const float4 *>(g_outm)[r*SMAIN+s];
        float delta = (s < SMAIN-1) ? (d[s+1]-d[s]) : 1e10f;
        float alpha = 1.f - expf(-fmaxf(o.x, 0.f)*delta);
        float ww = alpha*T; T *= (1.f - alpha + 1e-10f);
        w[s] = ww; wsum += ww; depth += ww*d[s];
        c0 += ww/(1.f+expf(-o.y)); c1 += ww/(1.f+expf(-o.z)); c2 += ww/(1.f+expf(-o.w));
    }
    float m[NG], sd[NG], ls[NG];
#pragma unroll
    for (int g = 0; g < NG; g++) { m[g] = g_means[r*NG+g]; sd[g] = g_stds[r*NG+g]; ls[g] = logf(sd[g]); }
    float qsum = 0.f;
    for (int s = 0; s < SMAIN; s++) {
        float qq = 0.f;
#pragma unroll
        for (int g = 0; g < NG; g++) {
            float t = (d[s]-m[g])/sd[g];
            qq += expf(-0.5f*t*t - ls[g]);
        }
        q[s] = qq*0.25f; qsum += q[s];
    }
    float kl = 0.f;
    for (int s = 0; s < SMAIN; s++) {
        float pw = w[s]/(wsum+EPSf), qn = q[s]/(qsum+EPSf);
        kl += pw*(logf(pw+EPSf) - logf(qn+EPSf));
    }
    float d2c = 1e30f;
#pragma unroll
    for (int g = 0; g < NG; g++) d2c = fminf(d2c, fabsf(m[g]-depth));
    float sc[3]; samp_img(src, pix[2*r], pix[2*r+1], sc);
    float closs = fabsf(sc[0]-c0) + fabsf(sc[1]-c1) + fabsf(sc[2]-c2);
    float cx = g_cam[3*r]*depth, cy = g_cam[3*r+1]*depth, cz = g_cam[3*r+2]*depth;
    float tx = s2t[0]*cx+s2t[1]*cy+s2t[2]*cz+s2t[3];
    float ty = s2t[4]*cx+s2t[5]*cy+s2t[6]*cz+s2t[7];
    float tz = s2t[8]*cx+s2t[9]*cy+s2t[10]*cz+s2t[11];
    float pxp = K4[0]*tx+K4[1]*ty+K4[2]*tz, pyp = K4[3]*tx+K4[4]*ty+K4[5]*tz, pzp = K4[6]*tx+K4[7]*ty+K4[8]*tz;
    float tc[3]; samp_img(tgt, pxp/(pzp+EPSf), pyp/(pzp+EPSf), tc);
    float mask = (depth < 30.f) ? 1.f : 0.f;
    g_kl[r] = kl; g_d2c[r] = d2c; g_colL[r] = closs;
    g_rn[r] = mask*(fabsf(tc[0]-sc[0]) + fabsf(tc[1]-sc[1]) + fabsf(tc[2]-sc[2]))*(1.f/3.f);
    g_rd[r] = mask;
    dout[1+r] = depth;
    dout[1+NRAYS+3*r+0] = c0; dout[1+NRAYS+3*r+1] = c1; dout[1+NRAYS+3*r+2] = c2;
}

__global__ void reduce_kernel(float *__restrict__ dout) {
    __shared__ float sm[5][256];
    int t = threadIdx.x;
    float a[5] = {0,0,0,0,0};
    for (int r = t; r < NRAYS; r += 256) {
        a[0] += g_kl[r]; a[1] += g_d2c[r]; a[2] += g_colL[r]; a[3] += g_rn[r]; a[4] += g_rd[r];
    }
    for (int c = 0; c < 5; c++) sm[c][t] = a[c];
    __syncthreads();
    for (int s = 128; s > 0; s >>= 1) {
        if (t < s) for (int c = 0; c < 5; c++) sm[c][t] += sm[c][t+s];
        __syncthreads();
    }
    if (t == 0)
        dout[0] = sm[0][0]*(1.f/NRAYS) + 0.01f*sm[1][0]*(1.f/NRAYS) +
                  sm[2][0]*(1.f/(3.f*NRAYS)) + sm[3][0]/(sm[4][0]+1e-6f);
}

extern "C" void kernel_launch(void* const* d_in, const int* in_sizes, int n_in,
                              void* d_out, int out_size) {
    const float *bev = (const float *)d_in[0];
    const float *src = (const float *)d_in[1];
    const float *tgt = (const float *)d_in[2];
    const float *K4  = (const float *)d_in[3];
    const float *s2i = (const float *)d_in[4];
    const float *s2t = (const float *)d_in[5];
    const float *pix = (const float *)d_in[6];
    const float *const *m1 = (const float *const *)&d_in[7];
    const float *const *m2 = (const float *const *)&d_in[17];
    float *dout = (float *)d_out;

    cudaFuncSetAttribute(decode_mma<true>,  cudaFuncAttributeMaxDynamicSharedMemorySize, DYNSM);
    cudaFuncSetAttribute(decode_mma<false>, cudaFuncAttributeMaxDynamicSharedMemorySize, DYNSM);

    prep_kernel<<<46032, 256>>>(bev, K4, s2i, pix,
                                m1[0], m1[2], m1[4], m1[6],
                                m2[0], m2[2], m2[4], m2[6]);
    decode_mma<true><<<NRAYS*NG/128, NT, DYNSM>>>(s2i, m2[1], m2[3], m2[5], m2[7], m2[8], m2[9]);
    gprep_kernel<<<16, 256>>>();
    decode_mma<false><<<NRAYS*SMAIN/128, NT, DYNSM>>>(s2i, m1[1], m1[3], m1[5], m1[7], m1[8], m1[9]);
    render_kernel<<<64, 64>>>(src, tgt, K4, s2t, pix, dout);
    reduce_kernel<<<1, 256>>>(dout);
}